// round 7
// baseline (speedup 1.0000x reference)
#include <cuda_runtime.h>

// Problem-fixed shapes
#define NN 50000
#define EE 800000
#define TT (EE + NN)      // real edges + self loops
#define H1 3
#define D1 192            // 3 heads x 64
#define D2 64
#define NG 128

// ---------------- scratch (device globals; no runtime allocation) -----------
__device__ float g_xp1[(size_t)NN * D1];   // layer1 lin output
__device__ float g_h1[(size_t)NN * D1];    // elu(agg + b1)
__device__ float g_asrc1v[(size_t)NN * 4]; // float4-padded src logits (3 heads + pad)
__device__ float g_adst1[NN * H1];
__device__ float g_xp2[(size_t)NN * D2];
__device__ float g_asrc2[NN];
__device__ float g_adst2[NN];
__device__ float g_pool[NG * D2];
__device__ float g_cnt[NG];
// CSR (rebuilt every call; deterministic content, order-free use)
__device__ int   g_deg[NN];        // degree, then reused as scatter cursor
__device__ int   g_row[NN + 1];    // row offsets
__device__ int   g_csrc[TT];       // src node per CSR slot

// ---------------- helpers ----------------------------------------------------
__device__ __forceinline__ float warp_sum(float s) {
    #pragma unroll
    for (int o = 16; o; o >>= 1) s += __shfl_xor_sync(0xFFFFFFFFu, s, o);
    return s;
}
__device__ __forceinline__ float lrelu(float a) { return fmaxf(a, 0.2f * a); }
__device__ __forceinline__ unsigned long long pk2(float lo, float hi) {
    unsigned long long r;
    asm("mov.b64 %0, {%1, %2};" : "=l"(r) : "f"(lo), "f"(hi));
    return r;
}
__device__ __forceinline__ void upk2(float& lo, float& hi, unsigned long long v) {
    asm("mov.b64 {%0, %1}, %2;" : "=f"(lo), "=f"(hi) : "l"(v));
}
__device__ __forceinline__ void fma2(unsigned long long& acc, unsigned long long a,
                                     unsigned long long b) {
    asm("fma.rn.f32x2 %0, %1, %2, %0;" : "+l"(acc) : "l"(a), "l"(b));
}

// ---------------- init (split in two so ncu -s 5 lands on k_gemm1) ----------
__global__ void k_init_a() {
    int i = blockIdx.x * blockDim.x + threadIdx.x;
    if (i < NN) g_deg[i] = 1;            // self loop
}
__global__ void k_init_b() {
    int i = blockIdx.x * blockDim.x + threadIdx.x;
    if (i < NG * D2) g_pool[i] = 0.f;
    if (i < NG) g_cnt[i] = 0.f;
}

// ---------------- CSR build ---------------------------------------------------
__global__ void k_hist(const int* __restrict__ dstp, int E) {
    int e = blockIdx.x * blockDim.x + threadIdx.x;
    if (e < E) atomicAdd(&g_deg[__ldg(dstp + e)], 1);
}

#define SCAN_T 1024
__global__ void k_scan() {   // exclusive prefix of g_deg -> g_row, + self-loop slot & cursor
    __shared__ int sums[SCAN_T];
    int t = threadIdx.x;
    const int chunk = (NN + SCAN_T - 1) / SCAN_T;   // 49
    int b0 = t * chunk, b1 = min(b0 + chunk, NN);
    int s = 0;
    for (int i = b0; i < b1; i++) s += g_deg[i];
    sums[t] = s;
    __syncthreads();
    for (int off = 1; off < SCAN_T; off <<= 1) {
        int v = (t >= off) ? sums[t - off] : 0;
        __syncthreads();
        sums[t] += v;
        __syncthreads();
    }
    int run = sums[t] - s;     // exclusive
    for (int i = b0; i < b1; i++) {
        int dg = g_deg[i];
        g_row[i]  = run;
        g_csrc[run] = i;       // self-loop slot
        g_deg[i]  = run + 1;   // scatter cursor (after self loop)
        run += dg;
    }
    if (t == SCAN_T - 1) g_row[NN] = run;
}

__global__ void k_scatter(const int* __restrict__ srcp, const int* __restrict__ dstp, int E) {
    int e = blockIdx.x * blockDim.x + threadIdx.x;
    if (e >= E) return;
    int pos = atomicAdd(&g_deg[__ldg(dstp + e)], 1);
    g_csrc[pos] = __ldg(srcp + e);
}

// ---------------- GEMM1: xp1 = x @ W1 (16 rows/block, 192 threads, FFMA2) ----
__global__ void k_gemm1(const float* __restrict__ x, const float* __restrict__ W1) {
    __shared__ float xs[64][20];   // [k][row], row-group start 16B aligned (80B stride)
    int t = threadIdx.x;           // 0..191 = output column
    int r0 = blockIdx.x * 16;
    unsigned long long acc[8];     // packed pairs: acc[p] = rows (2p, 2p+1)
    #pragma unroll
    for (int p = 0; p < 8; p++) acc[p] = 0ull;

    for (int k0 = 0; k0 < 128; k0 += 64) {
        __syncthreads();
        for (int i = t; i < 16 * 64; i += 192) {
            int c = i & 63, r = i >> 6;
            xs[c][r] = (r0 + r < NN) ? x[(size_t)(r0 + r) * 128 + k0 + c] : 0.f;
        }
        __syncthreads();
        #pragma unroll 8
        for (int kk = 0; kk < 64; kk++) {
            float w = W1[(k0 + kk) * 192 + t];
            unsigned long long w2 = pk2(w, w);
            const ulonglong2* xp = (const ulonglong2*)&xs[kk][0];
            ulonglong2 q0 = xp[0], q1 = xp[1], q2 = xp[2], q3 = xp[3];
            fma2(acc[0], q0.x, w2); fma2(acc[1], q0.y, w2);
            fma2(acc[2], q1.x, w2); fma2(acc[3], q1.y, w2);
            fma2(acc[4], q2.x, w2); fma2(acc[5], q2.y, w2);
            fma2(acc[6], q3.x, w2); fma2(acc[7], q3.y, w2);
        }
    }
    #pragma unroll
    for (int p = 0; p < 8; p++) {
        float lo, hi; upk2(lo, hi, acc[p]);
        int r = 2 * p;
        if (r0 + r     < NN) g_xp1[(size_t)(r0 + r)     * 192 + t] = lo;
        if (r0 + r + 1 < NN) g_xp1[(size_t)(r0 + r + 1) * 192 + t] = hi;
    }
}

// ---------------- attention dots, layer 1 (warp per node-head) ----------------
__global__ void k_att1(const float* __restrict__ att_src, const float* __restrict__ att_dst) {
    int idx = blockIdx.x * 8 + (threadIdx.x >> 5);
    if (idx >= NN * H1) return;
    int lane = threadIdx.x & 31;
    int n = idx / 3, h = idx % 3;
    size_t base = (size_t)n * 192 + h * 64;
    float v0 = g_xp1[base + lane], v1 = g_xp1[base + 32 + lane];
    float ss = v0 * att_src[h * 64 + lane] + v1 * att_src[h * 64 + 32 + lane];
    float sd = v0 * att_dst[h * 64 + lane] + v1 * att_dst[h * 64 + 32 + lane];
    ss = warp_sum(ss); sd = warp_sum(sd);
    if (lane == 0) { g_asrc1v[(size_t)n * 4 + h] = ss; g_adst1[idx] = sd; }
}

// ---------------- fused layer1: softmax(no-max) + aggregate + bias + elu ------
// warp per dst node; lane l owns cols l+32k, k=0..5 (2 cols per head); 2-edge unroll
__global__ void k_agg1(const float* __restrict__ b1) {
    int d = blockIdx.x * 8 + (threadIdx.x >> 5);
    if (d >= NN) return;
    int lane = threadIdx.x & 31;
    float ad0 = g_adst1[d * 3 + 0], ad1 = g_adst1[d * 3 + 1], ad2 = g_adst1[d * 3 + 2];
    float acc0 = 0.f, acc1 = 0.f, acc2 = 0.f, acc3 = 0.f, acc4 = 0.f, acc5 = 0.f;
    float den0 = 0.f, den1 = 0.f, den2 = 0.f;
    int beg = g_row[d], end = g_row[d + 1];
    int j = beg;
    for (; j + 2 <= end; j += 2) {
        int s0 = __ldg(g_csrc + j), s1 = __ldg(g_csrc + j + 1);
        float4 av0 = __ldg((const float4*)g_asrc1v + s0);
        float4 av1 = __ldg((const float4*)g_asrc1v + s1);
        const float* x0 = g_xp1 + (size_t)s0 * 192 + lane;
        const float* x1 = g_xp1 + (size_t)s1 * 192 + lane;
        float f00 = __ldg(x0),       f01 = __ldg(x0 + 32),  f02 = __ldg(x0 + 64);
        float f03 = __ldg(x0 + 96),  f04 = __ldg(x0 + 128), f05 = __ldg(x0 + 160);
        float f10 = __ldg(x1),       f11 = __ldg(x1 + 32),  f12 = __ldg(x1 + 64);
        float f13 = __ldg(x1 + 96),  f14 = __ldg(x1 + 128), f15 = __ldg(x1 + 160);
        float e00 = __expf(lrelu(av0.x + ad0));
        float e01 = __expf(lrelu(av0.y + ad1));
        float e02 = __expf(lrelu(av0.z + ad2));
        float e10 = __expf(lrelu(av1.x + ad0));
        float e11 = __expf(lrelu(av1.y + ad1));
        float e12 = __expf(lrelu(av1.z + ad2));
        den0 += e00 + e10; den1 += e01 + e11; den2 += e02 + e12;
        acc0 = fmaf(e00, f00, acc0); acc1 = fmaf(e00, f01, acc1);
        acc2 = fmaf(e01, f02, acc2); acc3 = fmaf(e01, f03, acc3);
        acc4 = fmaf(e02, f04, acc4); acc5 = fmaf(e02, f05, acc5);
        acc0 = fmaf(e10, f10, acc0); acc1 = fmaf(e10, f11, acc1);
        acc2 = fmaf(e11, f12, acc2); acc3 = fmaf(e11, f13, acc3);
        acc4 = fmaf(e12, f14, acc4); acc5 = fmaf(e12, f15, acc5);
    }
    if (j < end) {
        int s = __ldg(g_csrc + j);
        float4 av = __ldg((const float4*)g_asrc1v + s);
        const float* xr = g_xp1 + (size_t)s * 192 + lane;
        float e0 = __expf(lrelu(av.x + ad0));
        float e1 = __expf(lrelu(av.y + ad1));
        float e2 = __expf(lrelu(av.z + ad2));
        den0 += e0; den1 += e1; den2 += e2;
        acc0 = fmaf(e0, __ldg(xr),       acc0);
        acc1 = fmaf(e0, __ldg(xr + 32),  acc1);
        acc2 = fmaf(e1, __ldg(xr + 64),  acc2);
        acc3 = fmaf(e1, __ldg(xr + 96),  acc3);
        acc4 = fmaf(e2, __ldg(xr + 128), acc4);
        acc5 = fmaf(e2, __ldg(xr + 160), acc5);
    }
    float i0 = 1.f / fmaxf(den0, 1e-16f);
    float i1 = 1.f / fmaxf(den1, 1e-16f);
    float i2 = 1.f / fmaxf(den2, 1e-16f);
    float* o = g_h1 + (size_t)d * 192 + lane;
    float v;
    v = acc0 * i0 + b1[lane];       o[0]   = v > 0.f ? v : expm1f(v);
    v = acc1 * i0 + b1[lane + 32];  o[32]  = v > 0.f ? v : expm1f(v);
    v = acc2 * i1 + b1[lane + 64];  o[64]  = v > 0.f ? v : expm1f(v);
    v = acc3 * i1 + b1[lane + 96];  o[96]  = v > 0.f ? v : expm1f(v);
    v = acc4 * i2 + b1[lane + 128]; o[128] = v > 0.f ? v : expm1f(v);
    v = acc5 * i2 + b1[lane + 160]; o[160] = v > 0.f ? v : expm1f(v);
}

// ---------------- GEMM2: xp2 = h1 @ W2 (64 rows/block, 256 threads, FFMA2) ----
__global__ void k_gemm2(const float* __restrict__ W2) {
    __shared__ float xs[64][68];   // [k][row], 272B stride (16B multiple)
    int t = threadIdx.x;
    int col = t & 63, grp = t >> 6;      // grp -> rows [grp*16, grp*16+16)
    int r0 = blockIdx.x * 64;
    unsigned long long acc[8];
    #pragma unroll
    for (int p = 0; p < 8; p++) acc[p] = 0ull;

    for (int k0 = 0; k0 < 192; k0 += 64) {
        __syncthreads();
        for (int i = t; i < 64 * 64; i += 256) {
            int c = i & 63, r = i >> 6;
            xs[c][r] = (r0 + r < NN) ? g_h1[(size_t)(r0 + r) * 192 + k0 + c] : 0.f;
        }
        __syncthreads();
        #pragma unroll 8
        for (int kk = 0; kk < 64; kk++) {
            float w = W2[(k0 + kk) * 64 + col];
            unsigned long long w2 = pk2(w, w);
            const ulonglong2* xp = (const ulonglong2*)&xs[kk][grp * 16];
            ulonglong2 q0 = xp[0], q1 = xp[1], q2 = xp[2], q3 = xp[3];
            fma2(acc[0], q0.x, w2); fma2(acc[1], q0.y, w2);
            fma2(acc[2], q1.x, w2); fma2(acc[3], q1.y, w2);
            fma2(acc[4], q2.x, w2); fma2(acc[5], q2.y, w2);
            fma2(acc[6], q3.x, w2); fma2(acc[7], q3.y, w2);
        }
    }
    #pragma unroll
    for (int p = 0; p < 8; p++) {
        float lo, hi; upk2(lo, hi, acc[p]);
        int nr = r0 + grp * 16 + 2 * p;
        if (nr     < NN) g_xp2[(size_t)nr       * 64 + col] = lo;
        if (nr + 1 < NN) g_xp2[(size_t)(nr + 1) * 64 + col] = hi;
    }
}

// ---------------- attention dots, layer 2 (warp per node) ---------------------
__global__ void k_att2(const float* __restrict__ att_src, const float* __restrict__ att_dst) {
    int n = blockIdx.x * 8 + (threadIdx.x >> 5);
    if (n >= NN) return;
    int lane = threadIdx.x & 31;
    size_t base = (size_t)n * 64;
    float v0 = g_xp2[base + lane], v1 = g_xp2[base + 32 + lane];
    float ss = v0 * att_src[lane] + v1 * att_src[32 + lane];
    float sd = v0 * att_dst[lane] + v1 * att_dst[32 + lane];
    ss = warp_sum(ss); sd = warp_sum(sd);
    if (lane == 0) { g_asrc2[n] = ss; g_adst2[n] = sd; }
}

// ---------------- fused layer2: softmax + aggregate + bias + pool -------------
__global__ void k_agg2(const float* __restrict__ b2, const int* __restrict__ batch) {
    int d = blockIdx.x * 8 + (threadIdx.x >> 5);
    if (d >= NN) return;
    int lane = threadIdx.x & 31;
    float ad = g_adst2[d];
    float acc0 = 0.f, acc1 = 0.f, den = 0.f;
    int beg = g_row[d], end = g_row[d + 1];
    int j = beg;
    for (; j + 2 <= end; j += 2) {
        int s0 = __ldg(g_csrc + j), s1 = __ldg(g_csrc + j + 1);
        float a0 = __ldg(g_asrc2 + s0), a1 = __ldg(g_asrc2 + s1);
        const float* x0 = g_xp2 + (size_t)s0 * 64 + lane;
        const float* x1 = g_xp2 + (size_t)s1 * 64 + lane;
        float f00 = __ldg(x0), f01 = __ldg(x0 + 32);
        float f10 = __ldg(x1), f11 = __ldg(x1 + 32);
        float e0 = __expf(lrelu(a0 + ad));
        float e1 = __expf(lrelu(a1 + ad));
        den += e0 + e1;
        acc0 = fmaf(e0, f00, acc0); acc1 = fmaf(e0, f01, acc1);
        acc0 = fmaf(e1, f10, acc0); acc1 = fmaf(e1, f11, acc1);
    }
    if (j < end) {
        int s = __ldg(g_csrc + j);
        float e = __expf(lrelu(__ldg(g_asrc2 + s) + ad));
        den += e;
        const float* xr = g_xp2 + (size_t)s * 64 + lane;
        acc0 = fmaf(e, __ldg(xr),      acc0);
        acc1 = fmaf(e, __ldg(xr + 32), acc1);
    }
    float inv = 1.f / fmaxf(den, 1e-16f);
    int b = __ldg(batch + d);
    atomicAdd(&g_pool[b * 64 + lane],      acc0 * inv + b2[lane]);
    atomicAdd(&g_pool[b * 64 + lane + 32], acc1 * inv + b2[lane + 32]);
    if (lane == 0) atomicAdd(&g_cnt[b], 1.0f);
}

// ---------------- final: (pool/cnt) @ lin_W + lin_b ---------------------------
__global__ void k_final(const float* __restrict__ lin_W, const float* __restrict__ lin_b,
                        float* __restrict__ out) {
    int t = blockIdx.x * blockDim.x + threadIdx.x;
    if (t >= NG * 10) return;
    int g = t / 10, j = t % 10;
    float inv = 1.0f / fmaxf(g_cnt[g], 1.0f);
    float acc = lin_b[j];
    #pragma unroll 8
    for (int c = 0; c < 64; c++)
        acc += g_pool[g * 64 + c] * inv * lin_W[c * 10 + j];
    out[t] = acc;
}

// ---------------- host launch -------------------------------------------------
extern "C" void kernel_launch(void* const* d_in, const int* in_sizes, int n_in,
                              void* d_out, int out_size) {
    const float* x        = (const float*)d_in[0];
    const int*   ei       = (const int*)  d_in[1];
    const int*   batch    = (const int*)  d_in[2];
    const float* W1       = (const float*)d_in[3];
    const float* att_src1 = (const float*)d_in[4];
    const float* att_dst1 = (const float*)d_in[5];
    const float* b1       = (const float*)d_in[6];
    const float* W2       = (const float*)d_in[7];
    const float* att_src2 = (const float*)d_in[8];
    const float* att_dst2 = (const float*)d_in[9];
    const float* b2       = (const float*)d_in[10];
    const float* lin_W    = (const float*)d_in[11];
    const float* lin_b    = (const float*)d_in[12];
    float* out = (float*)d_out;

    int E = in_sizes[1] / 2;            // 800000
    const int* srcp = ei;
    const int* dstp = ei + E;

    // CSR build (dst-sorted adjacency incl. implicit self loops)
    k_init_a<<<(NN + 255) / 256, 256>>>();                 // launch 0
    k_init_b<<<(NG * D2 + 255) / 256, 256>>>();            // launch 1
    k_hist<<<(E + 255) / 256, 256>>>(dstp, E);             // launch 2
    k_scan<<<1, SCAN_T>>>();                               // launch 3
    k_scatter<<<(E + 255) / 256, 256>>>(srcp, dstp, E);    // launch 4

    // layer 1  (k_gemm1 is launch 5 -> ncu -s 5 -c 1 captures it)
    k_gemm1<<<(NN + 15) / 16, 192>>>(x, W1);
    k_att1<<<(NN * H1 + 7) / 8, 256>>>(att_src1, att_dst1);
    k_agg1<<<(NN + 7) / 8, 256>>>(b1);

    // layer 2
    k_gemm2<<<(NN + 63) / 64, 256>>>(W2);
    k_att2<<<(NN + 7) / 8, 256>>>(att_src2, att_dst2);
    k_agg2<<<(NN + 7) / 8, 256>>>(b2, batch);

    // readout
    k_final<<<10, 128>>>(lin_W, lin_b, out);
}

// round 8
// speedup vs baseline: 1.2619x; 1.2619x over previous
#include <cuda_runtime.h>

// Problem-fixed shapes
#define NN 50000
#define EE 800000
#define TT (EE + NN)      // real edges + self loops
#define H1 3
#define D1 192            // 3 heads x 64
#define D2 64
#define NG 128
#define NBLK ((NN + 255) / 256)   // 196 scan blocks

// ---------------- scratch (device globals; no runtime allocation) -----------
__device__ float g_xp1[(size_t)NN * D1];   // layer1 lin output
__device__ float g_h1[(size_t)NN * D1];    // elu(agg + b1)
__device__ float g_asrc1v[(size_t)NN * 4]; // float4-padded src logits (3 heads + pad)
__device__ float g_adst1[NN * H1];
__device__ float g_xp2[(size_t)NN * D2];
__device__ float g_asrc2[NN];
__device__ float g_adst2[NN];
__device__ float g_pool[NG * D2];
__device__ float g_cnt[NG];
// CSR (rebuilt every call; deterministic content, order-free use)
__device__ int   g_deg[NN];        // degree, then reused as scatter cursor
__device__ int   g_row[NN + 1];    // row offsets
__device__ int   g_csrc[TT];       // src node per CSR slot
__device__ int   g_bsum[NBLK];     // per-block degree sums
__device__ int   g_boff[NBLK];     // exclusive block offsets

// ---------------- helpers ----------------------------------------------------
__device__ __forceinline__ float warp_sum(float s) {
    #pragma unroll
    for (int o = 16; o; o >>= 1) s += __shfl_xor_sync(0xFFFFFFFFu, s, o);
    return s;
}
__device__ __forceinline__ float lrelu(float a) { return fmaxf(a, 0.2f * a); }
__device__ __forceinline__ unsigned long long pk2(float lo, float hi) {
    unsigned long long r;
    asm("mov.b64 %0, {%1, %2};" : "=l"(r) : "f"(lo), "f"(hi));
    return r;
}
__device__ __forceinline__ void upk2(float& lo, float& hi, unsigned long long v) {
    asm("mov.b64 {%0, %1}, %2;" : "=f"(lo), "=f"(hi) : "l"(v));
}
__device__ __forceinline__ void fma2(unsigned long long& acc, unsigned long long a,
                                     unsigned long long b) {
    asm("fma.rn.f32x2 %0, %1, %2, %0;" : "+l"(acc) : "l"(a), "l"(b));
}

// ---------------- init --------------------------------------------------------
__global__ void k_init_a() {
    int i = blockIdx.x * blockDim.x + threadIdx.x;
    if (i < NN) g_deg[i] = 1;            // self loop
}
__global__ void k_init_b() {
    int i = blockIdx.x * blockDim.x + threadIdx.x;
    if (i < NG * D2) g_pool[i] = 0.f;
    if (i < NG) g_cnt[i] = 0.f;
}

// ---------------- CSR build ---------------------------------------------------
__global__ void k_hist(const int* __restrict__ dstp, int E) {
    int e = blockIdx.x * blockDim.x + threadIdx.x;
    if (e < E) atomicAdd(&g_deg[__ldg(dstp + e)], 1);
}

// stage 1: per-block exclusive scan of degrees (256/block), block sum out
__global__ void k_scan_blk() {
    __shared__ int sd[256];
    int t = threadIdx.x;
    int i = blockIdx.x * 256 + t;
    int v = (i < NN) ? g_deg[i] : 0;
    sd[t] = v;
    __syncthreads();
    #pragma unroll
    for (int off = 1; off < 256; off <<= 1) {
        int u = (t >= off) ? sd[t - off] : 0;
        __syncthreads();
        sd[t] += u;
        __syncthreads();
    }
    if (i < NN) g_row[i] = sd[t] - v;          // exclusive within block
    if (t == 255) g_bsum[blockIdx.x] = sd[255];
}

// stage 2: 1-block exclusive scan of the 196 block sums (cheap: 256 threads)
__global__ void k_scan_top() {
    __shared__ int sd[256];
    int t = threadIdx.x;
    int v = (t < NBLK) ? g_bsum[t] : 0;
    sd[t] = v;
    __syncthreads();
    #pragma unroll
    for (int off = 1; off < 256; off <<= 1) {
        int u = (t >= off) ? sd[t - off] : 0;
        __syncthreads();
        sd[t] += u;
        __syncthreads();
    }
    if (t < NBLK) g_boff[t] = sd[t] - v;
    if (t == 255) g_row[NN] = sd[255];         // total = TT
}

// stage 3: add block offset, write self-loop slot + scatter cursor
__global__ void k_csr_fin() {
    int i = blockIdx.x * 256 + threadIdx.x;
    if (i >= NN) return;
    int r = g_row[i] + g_boff[blockIdx.x];
    g_row[i] = r;
    g_csrc[r] = i;          // self-loop slot
    g_deg[i] = r + 1;       // scatter cursor starts after self loop
}

__global__ void k_scatter(const int* __restrict__ srcp, const int* __restrict__ dstp, int E) {
    int e = blockIdx.x * blockDim.x + threadIdx.x;
    if (e >= E) return;
    int pos = atomicAdd(&g_deg[__ldg(dstp + e)], 1);
    g_csrc[pos] = __ldg(srcp + e);
}

// ---------------- GEMM1: xp1 = x @ W1 (16 rows/block, 192 threads, FFMA2) ----
__global__ void k_gemm1(const float* __restrict__ x, const float* __restrict__ W1) {
    __shared__ float xs[64][20];   // [k][row], row-group start 16B aligned (80B stride)
    int t = threadIdx.x;           // 0..191 = output column
    int r0 = blockIdx.x * 16;
    unsigned long long acc[8];     // packed pairs: acc[p] = rows (2p, 2p+1)
    #pragma unroll
    for (int p = 0; p < 8; p++) acc[p] = 0ull;

    for (int k0 = 0; k0 < 128; k0 += 64) {
        __syncthreads();
        for (int i = t; i < 16 * 64; i += 192) {
            int c = i & 63, r = i >> 6;
            xs[c][r] = (r0 + r < NN) ? x[(size_t)(r0 + r) * 128 + k0 + c] : 0.f;
        }
        __syncthreads();
        #pragma unroll 8
        for (int kk = 0; kk < 64; kk++) {
            float w = W1[(k0 + kk) * 192 + t];
            unsigned long long w2 = pk2(w, w);
            const ulonglong2* xp = (const ulonglong2*)&xs[kk][0];
            ulonglong2 q0 = xp[0], q1 = xp[1], q2 = xp[2], q3 = xp[3];
            fma2(acc[0], q0.x, w2); fma2(acc[1], q0.y, w2);
            fma2(acc[2], q1.x, w2); fma2(acc[3], q1.y, w2);
            fma2(acc[4], q2.x, w2); fma2(acc[5], q2.y, w2);
            fma2(acc[6], q3.x, w2); fma2(acc[7], q3.y, w2);
        }
    }
    #pragma unroll
    for (int p = 0; p < 8; p++) {
        float lo, hi; upk2(lo, hi, acc[p]);
        int r = 2 * p;
        if (r0 + r     < NN) g_xp1[(size_t)(r0 + r)     * 192 + t] = lo;
        if (r0 + r + 1 < NN) g_xp1[(size_t)(r0 + r + 1) * 192 + t] = hi;
    }
}

// ---------------- attention dots, layer 1 (warp per node-head) ----------------
__global__ void k_att1(const float* __restrict__ att_src, const float* __restrict__ att_dst) {
    int idx = blockIdx.x * 8 + (threadIdx.x >> 5);
    if (idx >= NN * H1) return;
    int lane = threadIdx.x & 31;
    int n = idx / 3, h = idx % 3;
    size_t base = (size_t)n * 192 + h * 64;
    float v0 = g_xp1[base + lane], v1 = g_xp1[base + 32 + lane];
    float ss = v0 * att_src[h * 64 + lane] + v1 * att_src[h * 64 + 32 + lane];
    float sd = v0 * att_dst[h * 64 + lane] + v1 * att_dst[h * 64 + 32 + lane];
    ss = warp_sum(ss); sd = warp_sum(sd);
    if (lane == 0) { g_asrc1v[(size_t)n * 4 + h] = ss; g_adst1[idx] = sd; }
}

// ---------------- fused layer1: softmax(no-max) + aggregate + bias + elu ------
// warp per dst node; lane l owns cols l+32k, k=0..5 (2 cols per head); 2-edge unroll
__global__ void k_agg1(const float* __restrict__ b1) {
    int d = blockIdx.x * 8 + (threadIdx.x >> 5);
    if (d >= NN) return;
    int lane = threadIdx.x & 31;
    float ad0 = g_adst1[d * 3 + 0], ad1 = g_adst1[d * 3 + 1], ad2 = g_adst1[d * 3 + 2];
    float acc0 = 0.f, acc1 = 0.f, acc2 = 0.f, acc3 = 0.f, acc4 = 0.f, acc5 = 0.f;
    float den0 = 0.f, den1 = 0.f, den2 = 0.f;
    int beg = g_row[d], end = g_row[d + 1];
    int j = beg;
    for (; j + 2 <= end; j += 2) {
        int s0 = __ldg(g_csrc + j), s1 = __ldg(g_csrc + j + 1);
        float4 av0 = __ldg((const float4*)g_asrc1v + s0);
        float4 av1 = __ldg((const float4*)g_asrc1v + s1);
        const float* x0 = g_xp1 + (size_t)s0 * 192 + lane;
        const float* x1 = g_xp1 + (size_t)s1 * 192 + lane;
        float f00 = __ldg(x0),       f01 = __ldg(x0 + 32),  f02 = __ldg(x0 + 64);
        float f03 = __ldg(x0 + 96),  f04 = __ldg(x0 + 128), f05 = __ldg(x0 + 160);
        float f10 = __ldg(x1),       f11 = __ldg(x1 + 32),  f12 = __ldg(x1 + 64);
        float f13 = __ldg(x1 + 96),  f14 = __ldg(x1 + 128), f15 = __ldg(x1 + 160);
        float e00 = __expf(lrelu(av0.x + ad0));
        float e01 = __expf(lrelu(av0.y + ad1));
        float e02 = __expf(lrelu(av0.z + ad2));
        float e10 = __expf(lrelu(av1.x + ad0));
        float e11 = __expf(lrelu(av1.y + ad1));
        float e12 = __expf(lrelu(av1.z + ad2));
        den0 += e00 + e10; den1 += e01 + e11; den2 += e02 + e12;
        acc0 = fmaf(e00, f00, acc0); acc1 = fmaf(e00, f01, acc1);
        acc2 = fmaf(e01, f02, acc2); acc3 = fmaf(e01, f03, acc3);
        acc4 = fmaf(e02, f04, acc4); acc5 = fmaf(e02, f05, acc5);
        acc0 = fmaf(e10, f10, acc0); acc1 = fmaf(e10, f11, acc1);
        acc2 = fmaf(e11, f12, acc2); acc3 = fmaf(e11, f13, acc3);
        acc4 = fmaf(e12, f14, acc4); acc5 = fmaf(e12, f15, acc5);
    }
    if (j < end) {
        int s = __ldg(g_csrc + j);
        float4 av = __ldg((const float4*)g_asrc1v + s);
        const float* xr = g_xp1 + (size_t)s * 192 + lane;
        float e0 = __expf(lrelu(av.x + ad0));
        float e1 = __expf(lrelu(av.y + ad1));
        float e2 = __expf(lrelu(av.z + ad2));
        den0 += e0; den1 += e1; den2 += e2;
        acc0 = fmaf(e0, __ldg(xr),       acc0);
        acc1 = fmaf(e0, __ldg(xr + 32),  acc1);
        acc2 = fmaf(e1, __ldg(xr + 64),  acc2);
        acc3 = fmaf(e1, __ldg(xr + 96),  acc3);
        acc4 = fmaf(e2, __ldg(xr + 128), acc4);
        acc5 = fmaf(e2, __ldg(xr + 160), acc5);
    }
    float i0 = 1.f / fmaxf(den0, 1e-16f);
    float i1 = 1.f / fmaxf(den1, 1e-16f);
    float i2 = 1.f / fmaxf(den2, 1e-16f);
    float* o = g_h1 + (size_t)d * 192 + lane;
    float v;
    v = acc0 * i0 + b1[lane];       o[0]   = v > 0.f ? v : expm1f(v);
    v = acc1 * i0 + b1[lane + 32];  o[32]  = v > 0.f ? v : expm1f(v);
    v = acc2 * i1 + b1[lane + 64];  o[64]  = v > 0.f ? v : expm1f(v);
    v = acc3 * i1 + b1[lane + 96];  o[96]  = v > 0.f ? v : expm1f(v);
    v = acc4 * i2 + b1[lane + 128]; o[128] = v > 0.f ? v : expm1f(v);
    v = acc5 * i2 + b1[lane + 160]; o[160] = v > 0.f ? v : expm1f(v);
}

// ---------------- GEMM2: xp2 = h1 @ W2 (64 rows/block, 256 threads, FFMA2) ----
__global__ void k_gemm2(const float* __restrict__ W2) {
    __shared__ float xs[64][68];   // [k][row], 272B stride (16B multiple)
    int t = threadIdx.x;
    int col = t & 63, grp = t >> 6;      // grp -> rows [grp*16, grp*16+16)
    int r0 = blockIdx.x * 64;
    unsigned long long acc[8];
    #pragma unroll
    for (int p = 0; p < 8; p++) acc[p] = 0ull;

    for (int k0 = 0; k0 < 192; k0 += 64) {
        __syncthreads();
        for (int i = t; i < 64 * 64; i += 256) {
            int c = i & 63, r = i >> 6;
            xs[c][r] = (r0 + r < NN) ? g_h1[(size_t)(r0 + r) * 192 + k0 + c] : 0.f;
        }
        __syncthreads();
        #pragma unroll 8
        for (int kk = 0; kk < 64; kk++) {
            float w = W2[(k0 + kk) * 64 + col];
            unsigned long long w2 = pk2(w, w);
            const ulonglong2* xp = (const ulonglong2*)&xs[kk][grp * 16];
            ulonglong2 q0 = xp[0], q1 = xp[1], q2 = xp[2], q3 = xp[3];
            fma2(acc[0], q0.x, w2); fma2(acc[1], q0.y, w2);
            fma2(acc[2], q1.x, w2); fma2(acc[3], q1.y, w2);
            fma2(acc[4], q2.x, w2); fma2(acc[5], q2.y, w2);
            fma2(acc[6], q3.x, w2); fma2(acc[7], q3.y, w2);
        }
    }
    #pragma unroll
    for (int p = 0; p < 8; p++) {
        float lo, hi; upk2(lo, hi, acc[p]);
        int nr = r0 + grp * 16 + 2 * p;
        if (nr     < NN) g_xp2[(size_t)nr       * 64 + col] = lo;
        if (nr + 1 < NN) g_xp2[(size_t)(nr + 1) * 64 + col] = hi;
    }
}

// ---------------- attention dots, layer 2 (warp per node) ---------------------
__global__ void k_att2(const float* __restrict__ att_src, const float* __restrict__ att_dst) {
    int n = blockIdx.x * 8 + (threadIdx.x >> 5);
    if (n >= NN) return;
    int lane = threadIdx.x & 31;
    size_t base = (size_t)n * 64;
    float v0 = g_xp2[base + lane], v1 = g_xp2[base + 32 + lane];
    float ss = v0 * att_src[lane] + v1 * att_src[32 + lane];
    float sd = v0 * att_dst[lane] + v1 * att_dst[32 + lane];
    ss = warp_sum(ss); sd = warp_sum(sd);
    if (lane == 0) { g_asrc2[n] = ss; g_adst2[n] = sd; }
}

// ---------------- fused layer2: softmax + aggregate + bias + pool -------------
__global__ void k_agg2(const float* __restrict__ b2, const int* __restrict__ batch) {
    int d = blockIdx.x * 8 + (threadIdx.x >> 5);
    if (d >= NN) return;
    int lane = threadIdx.x & 31;
    float ad = g_adst2[d];
    float acc0 = 0.f, acc1 = 0.f, den = 0.f;
    int beg = g_row[d], end = g_row[d + 1];
    int j = beg;
    for (; j + 2 <= end; j += 2) {
        int s0 = __ldg(g_csrc + j), s1 = __ldg(g_csrc + j + 1);
        float a0 = __ldg(g_asrc2 + s0), a1 = __ldg(g_asrc2 + s1);
        const float* x0 = g_xp2 + (size_t)s0 * 64 + lane;
        const float* x1 = g_xp2 + (size_t)s1 * 64 + lane;
        float f00 = __ldg(x0), f01 = __ldg(x0 + 32);
        float f10 = __ldg(x1), f11 = __ldg(x1 + 32);
        float e0 = __expf(lrelu(a0 + ad));
        float e1 = __expf(lrelu(a1 + ad));
        den += e0 + e1;
        acc0 = fmaf(e0, f00, acc0); acc1 = fmaf(e0, f01, acc1);
        acc0 = fmaf(e1, f10, acc0); acc1 = fmaf(e1, f11, acc1);
    }
    if (j < end) {
        int s = __ldg(g_csrc + j);
        float e = __expf(lrelu(__ldg(g_asrc2 + s) + ad));
        den += e;
        const float* xr = g_xp2 + (size_t)s * 64 + lane;
        acc0 = fmaf(e, __ldg(xr),      acc0);
        acc1 = fmaf(e, __ldg(xr + 32), acc1);
    }
    float inv = 1.f / fmaxf(den, 1e-16f);
    int b = __ldg(batch + d);
    atomicAdd(&g_pool[b * 64 + lane],      acc0 * inv + b2[lane]);
    atomicAdd(&g_pool[b * 64 + lane + 32], acc1 * inv + b2[lane + 32]);
    if (lane == 0) atomicAdd(&g_cnt[b], 1.0f);
}

// ---------------- final: (pool/cnt) @ lin_W + lin_b ---------------------------
__global__ void k_final(const float* __restrict__ lin_W, const float* __restrict__ lin_b,
                        float* __restrict__ out) {
    int t = blockIdx.x * blockDim.x + threadIdx.x;
    if (t >= NG * 10) return;
    int g = t / 10, j = t % 10;
    float inv = 1.0f / fmaxf(g_cnt[g], 1.0f);
    float acc = lin_b[j];
    #pragma unroll 8
    for (int c = 0; c < 64; c++)
        acc += g_pool[g * 64 + c] * inv * lin_W[c * 10 + j];
    out[t] = acc;
}

// ---------------- host launch -------------------------------------------------
extern "C" void kernel_launch(void* const* d_in, const int* in_sizes, int n_in,
                              void* d_out, int out_size) {
    const float* x        = (const float*)d_in[0];
    const int*   ei       = (const int*)  d_in[1];
    const int*   batch    = (const int*)  d_in[2];
    const float* W1       = (const float*)d_in[3];
    const float* att_src1 = (const float*)d_in[4];
    const float* att_dst1 = (const float*)d_in[5];
    const float* b1       = (const float*)d_in[6];
    const float* W2       = (const float*)d_in[7];
    const float* att_src2 = (const float*)d_in[8];
    const float* att_dst2 = (const float*)d_in[9];
    const float* b2       = (const float*)d_in[10];
    const float* lin_W    = (const float*)d_in[11];
    const float* lin_b    = (const float*)d_in[12];
    float* out = (float*)d_out;

    int E = in_sizes[1] / 2;            // 800000
    const int* srcp = ei;
    const int* dstp = ei + E;

    // launch index 3 = k_gemm1 (profiler capture lands on index 3)
    k_init_a<<<(NN + 255) / 256, 256>>>();                 // 0: deg=1
    k_init_b<<<(NG * D2 + 255) / 256, 256>>>();            // 1: pool=0
    k_hist<<<(E + 255) / 256, 256>>>(dstp, E);             // 2: degree histogram
    k_gemm1<<<(NN + 15) / 16, 192>>>(x, W1);               // 3: PROFILED
    k_scan_blk<<<NBLK, 256>>>();                           // 4: block scans
    k_scan_top<<<1, 256>>>();                              // 5: scan of block sums
    k_csr_fin<<<NBLK, 256>>>();                            // 6: offsets + self loop + cursor
    k_scatter<<<(E + 255) / 256, 256>>>(srcp, dstp, E);    // 7: fill CSR

    // layer 1
    k_att1<<<(NN * H1 + 7) / 8, 256>>>(att_src1, att_dst1);
    k_agg1<<<(NN + 7) / 8, 256>>>(b1);

    // layer 2
    k_gemm2<<<(NN + 63) / 64, 256>>>(W2);
    k_att2<<<(NN + 7) / 8, 256>>>(att_src2, att_dst2);
    k_agg2<<<(NN + 7) / 8, 256>>>(b2, batch);

    // readout
    k_final<<<10, 128>>>(lin_W, lin_b, out);
}

// round 9
// speedup vs baseline: 1.2773x; 1.0122x over previous
#include <cuda_runtime.h>

// Problem-fixed shapes
#define NN 50000
#define EE 800000
#define TT (EE + NN)      // real edges + self loops
#define H1 3
#define D1 192            // 3 heads x 64
#define D2 64
#define NG 128
#define NBLK ((NN + 255) / 256)   // 196 scan blocks

// ---------------- scratch (device globals; no runtime allocation) -----------
__device__ float g_xp1[(size_t)NN * D1];   // layer1 lin output
__device__ float g_h1[(size_t)NN * D1];    // elu(agg + b1)
__device__ float g_asrc1v[(size_t)NN * 4]; // float4-padded src logits (3 heads + pad)
__device__ float g_adst1[NN * H1];
__device__ float g_xp2[(size_t)NN * D2];
__device__ float g_asrc2[NN];
__device__ float g_adst2[NN];
__device__ float g_pool[NG * D2];
__device__ float g_cnt[NG];
// CSR (rebuilt every call; deterministic content, order-free use)
__device__ int   g_deg[NN];        // degree, then reused as scatter cursor
__device__ int   g_row[NN + 1];    // row offsets
__device__ int   g_csrc[TT];       // src node per CSR slot
__device__ int   g_bsum[NBLK];     // per-block degree sums
__device__ int   g_boff[NBLK];     // exclusive block offsets

// ---------------- helpers ----------------------------------------------------
__device__ __forceinline__ float warp_sum(float s) {
    #pragma unroll
    for (int o = 16; o; o >>= 1) s += __shfl_xor_sync(0xFFFFFFFFu, s, o);
    return s;
}
__device__ __forceinline__ float lrelu(float a) { return fmaxf(a, 0.2f * a); }
__device__ __forceinline__ unsigned long long pk2(float lo, float hi) {
    unsigned long long r;
    asm("mov.b64 %0, {%1, %2};" : "=l"(r) : "f"(lo), "f"(hi));
    return r;
}
__device__ __forceinline__ void upk2(float& lo, float& hi, unsigned long long v) {
    asm("mov.b64 {%0, %1}, %2;" : "=f"(lo), "=f"(hi) : "l"(v));
}
__device__ __forceinline__ void fma2(unsigned long long& acc, unsigned long long a,
                                     unsigned long long b) {
    asm("fma.rn.f32x2 %0, %1, %2, %0;" : "+l"(acc) : "l"(a), "l"(b));
}

// ---------------- init --------------------------------------------------------
__global__ void k_init_a() {
    int i = blockIdx.x * blockDim.x + threadIdx.x;
    if (i < NN) g_deg[i] = 1;            // self loop
}
__global__ void k_init_b() {
    int i = blockIdx.x * blockDim.x + threadIdx.x;
    if (i < NG * D2) g_pool[i] = 0.f;
    if (i < NG) g_cnt[i] = 0.f;
}

// ---------------- CSR build ---------------------------------------------------
__global__ void k_hist(const int* __restrict__ dstp, int E) {
    int e = blockIdx.x * blockDim.x + threadIdx.x;
    if (e < E) atomicAdd(&g_deg[__ldg(dstp + e)], 1);
}

// stage 1: per-block exclusive scan of degrees (256/block), block sum out
__global__ void k_scan_blk() {
    __shared__ int sd[256];
    int t = threadIdx.x;
    int i = blockIdx.x * 256 + t;
    int v = (i < NN) ? g_deg[i] : 0;
    sd[t] = v;
    __syncthreads();
    #pragma unroll
    for (int off = 1; off < 256; off <<= 1) {
        int u = (t >= off) ? sd[t - off] : 0;
        __syncthreads();
        sd[t] += u;
        __syncthreads();
    }
    if (i < NN) g_row[i] = sd[t] - v;          // exclusive within block
    if (t == 255) g_bsum[blockIdx.x] = sd[255];
}

// stage 2: 1-block exclusive scan of the 196 block sums
__global__ void k_scan_top() {
    __shared__ int sd[256];
    int t = threadIdx.x;
    int v = (t < NBLK) ? g_bsum[t] : 0;
    sd[t] = v;
    __syncthreads();
    #pragma unroll
    for (int off = 1; off < 256; off <<= 1) {
        int u = (t >= off) ? sd[t - off] : 0;
        __syncthreads();
        sd[t] += u;
        __syncthreads();
    }
    if (t < NBLK) g_boff[t] = sd[t] - v;
    if (t == 255) g_row[NN] = sd[255];         // total = TT
}

// stage 3: add block offset, write self-loop slot + scatter cursor
__global__ void k_csr_fin() {
    int i = blockIdx.x * 256 + threadIdx.x;
    if (i >= NN) return;
    int r = g_row[i] + g_boff[blockIdx.x];
    g_row[i] = r;
    g_csrc[r] = i;          // self-loop slot
    g_deg[i] = r + 1;       // scatter cursor starts after self loop
}

__global__ void k_scatter(const int* __restrict__ srcp, const int* __restrict__ dstp, int E) {
    int e = blockIdx.x * blockDim.x + threadIdx.x;
    if (e >= E) return;
    int pos = atomicAdd(&g_deg[__ldg(dstp + e)], 1);
    g_csrc[pos] = __ldg(srcp + e);
}

// ---------------- GEMM1: xp1 = x @ W1 ----------------------------------------
// 96 threads/block, tile 32 rows x 192 cols; thread t owns cols (2t, 2t+1),
// all 32 rows. Per k-step: 8 LDS.128 (broadcast) + 1 LDG.64 -> 32 FFMA2.
__global__ void k_gemm1(const float* __restrict__ x, const float* __restrict__ W1) {
    __shared__ float xs[64][36];     // [k][row], 144B row stride (16B multiple)
    int t = threadIdx.x;             // 0..95
    int r0 = blockIdx.x * 32;
    unsigned long long accA[16], accB[16];   // accA: col 2t, accB: col 2t+1; rows packed (2p,2p+1)
    #pragma unroll
    for (int p = 0; p < 16; p++) { accA[p] = 0ull; accB[p] = 0ull; }

    for (int k0 = 0; k0 < 128; k0 += 64) {
        __syncthreads();
        for (int i = t; i < 32 * 64; i += 96) {
            int c = i & 63, r = i >> 6;
            xs[c][r] = (r0 + r < NN) ? x[(size_t)(r0 + r) * 128 + k0 + c] : 0.f;
        }
        __syncthreads();
        #pragma unroll 2
        for (int kk = 0; kk < 64; kk++) {
            float2 wv = *(const float2*)&W1[(k0 + kk) * 192 + 2 * t];
            unsigned long long wa = pk2(wv.x, wv.x);
            unsigned long long wb = pk2(wv.y, wv.y);
            const ulonglong2* xp = (const ulonglong2*)&xs[kk][0];
            ulonglong2 v0 = xp[0], v1 = xp[1], v2 = xp[2], v3 = xp[3];
            ulonglong2 v4 = xp[4], v5 = xp[5], v6 = xp[6], v7 = xp[7];
            fma2(accA[0],  v0.x, wa); fma2(accB[0],  v0.x, wb);
            fma2(accA[1],  v0.y, wa); fma2(accB[1],  v0.y, wb);
            fma2(accA[2],  v1.x, wa); fma2(accB[2],  v1.x, wb);
            fma2(accA[3],  v1.y, wa); fma2(accB[3],  v1.y, wb);
            fma2(accA[4],  v2.x, wa); fma2(accB[4],  v2.x, wb);
            fma2(accA[5],  v2.y, wa); fma2(accB[5],  v2.y, wb);
            fma2(accA[6],  v3.x, wa); fma2(accB[6],  v3.x, wb);
            fma2(accA[7],  v3.y, wa); fma2(accB[7],  v3.y, wb);
            fma2(accA[8],  v4.x, wa); fma2(accB[8],  v4.x, wb);
            fma2(accA[9],  v4.y, wa); fma2(accB[9],  v4.y, wb);
            fma2(accA[10], v5.x, wa); fma2(accB[10], v5.x, wb);
            fma2(accA[11], v5.y, wa); fma2(accB[11], v5.y, wb);
            fma2(accA[12], v6.x, wa); fma2(accB[12], v6.x, wb);
            fma2(accA[13], v6.y, wa); fma2(accB[13], v6.y, wb);
            fma2(accA[14], v7.x, wa); fma2(accB[14], v7.x, wb);
            fma2(accA[15], v7.y, wa); fma2(accB[15], v7.y, wb);
        }
    }
    #pragma unroll
    for (int p = 0; p < 16; p++) {
        float alo, ahi, blo, bhi;
        upk2(alo, ahi, accA[p]);
        upk2(blo, bhi, accB[p]);
        int r = r0 + 2 * p;
        if (r < NN)
            *(float2*)&g_xp1[(size_t)r * 192 + 2 * t] = make_float2(alo, blo);
        if (r + 1 < NN)
            *(float2*)&g_xp1[(size_t)(r + 1) * 192 + 2 * t] = make_float2(ahi, bhi);
    }
}

// ---------------- attention dots, layer 1 (warp per node-head) ----------------
__global__ void k_att1(const float* __restrict__ att_src, const float* __restrict__ att_dst) {
    int idx = blockIdx.x * 8 + (threadIdx.x >> 5);
    if (idx >= NN * H1) return;
    int lane = threadIdx.x & 31;
    int n = idx / 3, h = idx % 3;
    size_t base = (size_t)n * 192 + h * 64;
    float v0 = g_xp1[base + lane], v1 = g_xp1[base + 32 + lane];
    float ss = v0 * att_src[h * 64 + lane] + v1 * att_src[h * 64 + 32 + lane];
    float sd = v0 * att_dst[h * 64 + lane] + v1 * att_dst[h * 64 + 32 + lane];
    ss = warp_sum(ss); sd = warp_sum(sd);
    if (lane == 0) { g_asrc1v[(size_t)n * 4 + h] = ss; g_adst1[idx] = sd; }
}

// ---------------- fused layer1: softmax(no-max) + aggregate + bias + elu ------
__global__ void k_agg1(const float* __restrict__ b1) {
    int d = blockIdx.x * 8 + (threadIdx.x >> 5);
    if (d >= NN) return;
    int lane = threadIdx.x & 31;
    float ad0 = g_adst1[d * 3 + 0], ad1 = g_adst1[d * 3 + 1], ad2 = g_adst1[d * 3 + 2];
    float acc0 = 0.f, acc1 = 0.f, acc2 = 0.f, acc3 = 0.f, acc4 = 0.f, acc5 = 0.f;
    float den0 = 0.f, den1 = 0.f, den2 = 0.f;
    int beg = g_row[d], end = g_row[d + 1];
    int j = beg;
    for (; j + 2 <= end; j += 2) {
        int s0 = __ldg(g_csrc + j), s1 = __ldg(g_csrc + j + 1);
        float4 av0 = __ldg((const float4*)g_asrc1v + s0);
        float4 av1 = __ldg((const float4*)g_asrc1v + s1);
        const float* x0 = g_xp1 + (size_t)s0 * 192 + lane;
        const float* x1 = g_xp1 + (size_t)s1 * 192 + lane;
        float f00 = __ldg(x0),       f01 = __ldg(x0 + 32),  f02 = __ldg(x0 + 64);
        float f03 = __ldg(x0 + 96),  f04 = __ldg(x0 + 128), f05 = __ldg(x0 + 160);
        float f10 = __ldg(x1),       f11 = __ldg(x1 + 32),  f12 = __ldg(x1 + 64);
        float f13 = __ldg(x1 + 96),  f14 = __ldg(x1 + 128), f15 = __ldg(x1 + 160);
        float e00 = __expf(lrelu(av0.x + ad0));
        float e01 = __expf(lrelu(av0.y + ad1));
        float e02 = __expf(lrelu(av0.z + ad2));
        float e10 = __expf(lrelu(av1.x + ad0));
        float e11 = __expf(lrelu(av1.y + ad1));
        float e12 = __expf(lrelu(av1.z + ad2));
        den0 += e00 + e10; den1 += e01 + e11; den2 += e02 + e12;
        acc0 = fmaf(e00, f00, acc0); acc1 = fmaf(e00, f01, acc1);
        acc2 = fmaf(e01, f02, acc2); acc3 = fmaf(e01, f03, acc3);
        acc4 = fmaf(e02, f04, acc4); acc5 = fmaf(e02, f05, acc5);
        acc0 = fmaf(e10, f10, acc0); acc1 = fmaf(e10, f11, acc1);
        acc2 = fmaf(e11, f12, acc2); acc3 = fmaf(e11, f13, acc3);
        acc4 = fmaf(e12, f14, acc4); acc5 = fmaf(e12, f15, acc5);
    }
    if (j < end) {
        int s = __ldg(g_csrc + j);
        float4 av = __ldg((const float4*)g_asrc1v + s);
        const float* xr = g_xp1 + (size_t)s * 192 + lane;
        float e0 = __expf(lrelu(av.x + ad0));
        float e1 = __expf(lrelu(av.y + ad1));
        float e2 = __expf(lrelu(av.z + ad2));
        den0 += e0; den1 += e1; den2 += e2;
        acc0 = fmaf(e0, __ldg(xr),       acc0);
        acc1 = fmaf(e0, __ldg(xr + 32),  acc1);
        acc2 = fmaf(e1, __ldg(xr + 64),  acc2);
        acc3 = fmaf(e1, __ldg(xr + 96),  acc3);
        acc4 = fmaf(e2, __ldg(xr + 128), acc4);
        acc5 = fmaf(e2, __ldg(xr + 160), acc5);
    }
    float i0 = 1.f / fmaxf(den0, 1e-16f);
    float i1 = 1.f / fmaxf(den1, 1e-16f);
    float i2 = 1.f / fmaxf(den2, 1e-16f);
    float* o = g_h1 + (size_t)d * 192 + lane;
    float v;
    v = acc0 * i0 + b1[lane];       o[0]   = v > 0.f ? v : expm1f(v);
    v = acc1 * i0 + b1[lane + 32];  o[32]  = v > 0.f ? v : expm1f(v);
    v = acc2 * i1 + b1[lane + 64];  o[64]  = v > 0.f ? v : expm1f(v);
    v = acc3 * i1 + b1[lane + 96];  o[96]  = v > 0.f ? v : expm1f(v);
    v = acc4 * i2 + b1[lane + 128]; o[128] = v > 0.f ? v : expm1f(v);
    v = acc5 * i2 + b1[lane + 160]; o[160] = v > 0.f ? v : expm1f(v);
}

// ---------------- GEMM2: xp2 = h1 @ W2 ----------------------------------------
// 128 threads/block, tile 64 rows x 64 cols; thread = (grp = 16 rows) x 2 cols.
// Per k-step: 4 LDS.128 + 1 LDG.64 -> 16 FFMA2.
__global__ void k_gemm2(const float* __restrict__ W2) {
    __shared__ float xs[64][68];   // [k][row], 272B stride (16B multiple)
    int t = threadIdx.x;
    int tc = t & 31;               // cols 2tc, 2tc+1
    int grp = t >> 5;              // rows [grp*16, grp*16+16)
    int r0 = blockIdx.x * 64;
    unsigned long long accA[8], accB[8];
    #pragma unroll
    for (int p = 0; p < 8; p++) { accA[p] = 0ull; accB[p] = 0ull; }

    for (int k0 = 0; k0 < 192; k0 += 64) {
        __syncthreads();
        for (int i = t; i < 64 * 64; i += 128) {
            int c = i & 63, r = i >> 6;
            xs[c][r] = (r0 + r < NN) ? g_h1[(size_t)(r0 + r) * 192 + k0 + c] : 0.f;
        }
        __syncthreads();
        #pragma unroll 2
        for (int kk = 0; kk < 64; kk++) {
            float2 wv = *(const float2*)&W2[(k0 + kk) * 64 + 2 * tc];
            unsigned long long wa = pk2(wv.x, wv.x);
            unsigned long long wb = pk2(wv.y, wv.y);
            const ulonglong2* xp = (const ulonglong2*)&xs[kk][grp * 16];
            ulonglong2 v0 = xp[0], v1 = xp[1], v2 = xp[2], v3 = xp[3];
            fma2(accA[0], v0.x, wa); fma2(accB[0], v0.x, wb);
            fma2(accA[1], v0.y, wa); fma2(accB[1], v0.y, wb);
            fma2(accA[2], v1.x, wa); fma2(accB[2], v1.x, wb);
            fma2(accA[3], v1.y, wa); fma2(accB[3], v1.y, wb);
            fma2(accA[4], v2.x, wa); fma2(accB[4], v2.x, wb);
            fma2(accA[5], v2.y, wa); fma2(accB[5], v2.y, wb);
            fma2(accA[6], v3.x, wa); fma2(accB[6], v3.x, wb);
            fma2(accA[7], v3.y, wa); fma2(accB[7], v3.y, wb);
        }
    }
    #pragma unroll
    for (int p = 0; p < 8; p++) {
        float alo, ahi, blo, bhi;
        upk2(alo, ahi, accA[p]);
        upk2(blo, bhi, accB[p]);
        int r = r0 + grp * 16 + 2 * p;
        if (r < NN)
            *(float2*)&g_xp2[(size_t)r * 64 + 2 * tc] = make_float2(alo, blo);
        if (r + 1 < NN)
            *(float2*)&g_xp2[(size_t)(r + 1) * 64 + 2 * tc] = make_float2(ahi, bhi);
    }
}

// ---------------- attention dots, layer 2 (warp per node) ---------------------
__global__ void k_att2(const float* __restrict__ att_src, const float* __restrict__ att_dst) {
    int n = blockIdx.x * 8 + (threadIdx.x >> 5);
    if (n >= NN) return;
    int lane = threadIdx.x & 31;
    size_t base = (size_t)n * 64;
    float v0 = g_xp2[base + lane], v1 = g_xp2[base + 32 + lane];
    float ss = v0 * att_src[lane] + v1 * att_src[32 + lane];
    float sd = v0 * att_dst[lane] + v1 * att_dst[32 + lane];
    ss = warp_sum(ss); sd = warp_sum(sd);
    if (lane == 0) { g_asrc2[n] = ss; g_adst2[n] = sd; }
}

// ---------------- fused layer2: softmax + aggregate + bias + pool -------------
__global__ void k_agg2(const float* __restrict__ b2, const int* __restrict__ batch) {
    int d = blockIdx.x * 8 + (threadIdx.x >> 5);
    if (d >= NN) return;
    int lane = threadIdx.x & 31;
    float ad = g_adst2[d];
    float acc0 = 0.f, acc1 = 0.f, den = 0.f;
    int beg = g_row[d], end = g_row[d + 1];
    int j = beg;
    for (; j + 2 <= end; j += 2) {
        int s0 = __ldg(g_csrc + j), s1 = __ldg(g_csrc + j + 1);
        float a0 = __ldg(g_asrc2 + s0), a1 = __ldg(g_asrc2 + s1);
        const float* x0 = g_xp2 + (size_t)s0 * 64 + lane;
        const float* x1 = g_xp2 + (size_t)s1 * 64 + lane;
        float f00 = __ldg(x0), f01 = __ldg(x0 + 32);
        float f10 = __ldg(x1), f11 = __ldg(x1 + 32);
        float e0 = __expf(lrelu(a0 + ad));
        float e1 = __expf(lrelu(a1 + ad));
        den += e0 + e1;
        acc0 = fmaf(e0, f00, acc0); acc1 = fmaf(e0, f01, acc1);
        acc0 = fmaf(e1, f10, acc0); acc1 = fmaf(e1, f11, acc1);
    }
    if (j < end) {
        int s = __ldg(g_csrc + j);
        float e = __expf(lrelu(__ldg(g_asrc2 + s) + ad));
        den += e;
        const float* xr = g_xp2 + (size_t)s * 64 + lane;
        acc0 = fmaf(e, __ldg(xr),      acc0);
        acc1 = fmaf(e, __ldg(xr + 32), acc1);
    }
    float inv = 1.f / fmaxf(den, 1e-16f);
    int b = __ldg(batch + d);
    atomicAdd(&g_pool[b * 64 + lane],      acc0 * inv + b2[lane]);
    atomicAdd(&g_pool[b * 64 + lane + 32], acc1 * inv + b2[lane + 32]);
    if (lane == 0) atomicAdd(&g_cnt[b], 1.0f);
}

// ---------------- final: (pool/cnt) @ lin_W + lin_b ---------------------------
__global__ void k_final(const float* __restrict__ lin_W, const float* __restrict__ lin_b,
                        float* __restrict__ out) {
    int t = blockIdx.x * blockDim.x + threadIdx.x;
    if (t >= NG * 10) return;
    int g = t / 10, j = t % 10;
    float inv = 1.0f / fmaxf(g_cnt[g], 1.0f);
    float acc = lin_b[j];
    #pragma unroll 8
    for (int c = 0; c < 64; c++)
        acc += g_pool[g * 64 + c] * inv * lin_W[c * 10 + j];
    out[t] = acc;
}

// ---------------- host launch -------------------------------------------------
extern "C" void kernel_launch(void* const* d_in, const int* in_sizes, int n_in,
                              void* d_out, int out_size) {
    const float* x        = (const float*)d_in[0];
    const int*   ei       = (const int*)  d_in[1];
    const int*   batch    = (const int*)  d_in[2];
    const float* W1       = (const float*)d_in[3];
    const float* att_src1 = (const float*)d_in[4];
    const float* att_dst1 = (const float*)d_in[5];
    const float* b1       = (const float*)d_in[6];
    const float* W2       = (const float*)d_in[7];
    const float* att_src2 = (const float*)d_in[8];
    const float* att_dst2 = (const float*)d_in[9];
    const float* b2       = (const float*)d_in[10];
    const float* lin_W    = (const float*)d_in[11];
    const float* lin_b    = (const float*)d_in[12];
    float* out = (float*)d_out;

    int E = in_sizes[1] / 2;            // 800000
    const int* srcp = ei;
    const int* dstp = ei + E;

    // launch index 3 = k_gemm1 (profiler capture lands on index 3)
    k_init_a<<<(NN + 255) / 256, 256>>>();                 // 0: deg=1
    k_init_b<<<(NG * D2 + 255) / 256, 256>>>();            // 1: pool=0
    k_hist<<<(E + 255) / 256, 256>>>(dstp, E);             // 2: degree histogram
    k_gemm1<<<(NN + 31) / 32, 96>>>(x, W1);                // 3: PROFILED
    k_scan_blk<<<NBLK, 256>>>();                           // 4: block scans
    k_scan_top<<<1, 256>>>();                              // 5: scan of block sums
    k_csr_fin<<<NBLK, 256>>>();                            // 6: offsets + self loop + cursor
    k_scatter<<<(E + 255) / 256, 256>>>(srcp, dstp, E);    // 7: fill CSR

    // layer 1
    k_att1<<<(NN * H1 + 7) / 8, 256>>>(att_src1, att_dst1);
    k_agg1<<<(NN + 7) / 8, 256>>>(b1);

    // layer 2
    k_gemm2<<<(NN + 63) / 64, 128>>>(W2);
    k_att2<<<(NN + 7) / 8, 256>>>(att_src2, att_dst2);
    k_agg2<<<(NN + 7) / 8, 256>>>(b2, batch);

    // readout
    k_final<<<10, 128>>>(lin_W, lin_b, out);
}

// round 10
// speedup vs baseline: 1.3722x; 1.0743x over previous
#include <cuda_runtime.h>

// Problem-fixed shapes
#define NN 50000
#define EE 800000
#define TT (EE + NN)      // real edges + self loops
#define H1 3
#define D1 192            // 3 heads x 64
#define D2 64
#define NG 128
#define NBLK ((NN + 255) / 256)   // 196 scan blocks

// ---------------- scratch (device globals; no runtime allocation) -----------
__device__ float g_xp1[(size_t)NN * D1];   // layer1 lin output
__device__ float g_h1[(size_t)NN * D1];    // elu(agg + b1)
__device__ float g_asrc1v[(size_t)NN * 4]; // float4-padded src logits (3 heads + pad)
__device__ float g_adst1[NN * H1];
__device__ float g_xp2[(size_t)NN * D2];
__device__ float g_asrc2[NN];
__device__ float g_adst2[NN];
__device__ float g_pool[NG * D2];
__device__ float g_cnt[NG];
// CSR (rebuilt every call; deterministic content, order-free use)
__device__ int   g_deg[NN];        // degree, then reused as scatter cursor
__device__ int   g_row[NN + 1];    // row offsets
__device__ int   g_csrc[TT];       // src node per CSR slot
__device__ int   g_bsum[NBLK];     // per-block degree sums
__device__ int   g_boff[NBLK];     // exclusive block offsets

// ---------------- helpers ----------------------------------------------------
__device__ __forceinline__ float warp_sum(float s) {
    #pragma unroll
    for (int o = 16; o; o >>= 1) s += __shfl_xor_sync(0xFFFFFFFFu, s, o);
    return s;
}
__device__ __forceinline__ float lrelu(float a) { return fmaxf(a, 0.2f * a); }
__device__ __forceinline__ unsigned long long pk2(float lo, float hi) {
    unsigned long long r;
    asm("mov.b64 %0, {%1, %2};" : "=l"(r) : "f"(lo), "f"(hi));
    return r;
}
__device__ __forceinline__ void upk2(float& lo, float& hi, unsigned long long v) {
    asm("mov.b64 {%0, %1}, %2;" : "=f"(lo), "=f"(hi) : "l"(v));
}
__device__ __forceinline__ void fma2(unsigned long long& acc, unsigned long long a,
                                     unsigned long long b) {
    asm("fma.rn.f32x2 %0, %1, %2, %0;" : "+l"(acc) : "l"(a), "l"(b));
}

// ---------------- init --------------------------------------------------------
__global__ void k_init_a() {
    int i = blockIdx.x * blockDim.x + threadIdx.x;
    if (i < NN) g_deg[i] = 1;            // self loop
}
__global__ void k_init_b() {
    int i = blockIdx.x * blockDim.x + threadIdx.x;
    if (i < NG * D2) g_pool[i] = 0.f;
    if (i < NG) g_cnt[i] = 0.f;
}

// ---------------- CSR build ---------------------------------------------------
__global__ void k_hist(const int* __restrict__ dstp, int E) {
    int e = blockIdx.x * blockDim.x + threadIdx.x;
    if (e < E) atomicAdd(&g_deg[__ldg(dstp + e)], 1);
}

// stage 1: per-block exclusive scan of degrees (256/block), block sum out
__global__ void k_scan_blk() {
    __shared__ int sd[256];
    int t = threadIdx.x;
    int i = blockIdx.x * 256 + t;
    int v = (i < NN) ? g_deg[i] : 0;
    sd[t] = v;
    __syncthreads();
    #pragma unroll
    for (int off = 1; off < 256; off <<= 1) {
        int u = (t >= off) ? sd[t - off] : 0;
        __syncthreads();
        sd[t] += u;
        __syncthreads();
    }
    if (i < NN) g_row[i] = sd[t] - v;          // exclusive within block
    if (t == 255) g_bsum[blockIdx.x] = sd[255];
}

// stage 2: 1-block exclusive scan of the 196 block sums
__global__ void k_scan_top() {
    __shared__ int sd[256];
    int t = threadIdx.x;
    int v = (t < NBLK) ? g_bsum[t] : 0;
    sd[t] = v;
    __syncthreads();
    #pragma unroll
    for (int off = 1; off < 256; off <<= 1) {
        int u = (t >= off) ? sd[t - off] : 0;
        __syncthreads();
        sd[t] += u;
        __syncthreads();
    }
    if (t < NBLK) g_boff[t] = sd[t] - v;
    if (t == 255) g_row[NN] = sd[255];         // total = TT
}

// stage 3: add block offset, write self-loop slot + scatter cursor
__global__ void k_csr_fin() {
    int i = blockIdx.x * 256 + threadIdx.x;
    if (i >= NN) return;
    int r = g_row[i] + g_boff[blockIdx.x];
    g_row[i] = r;
    g_csrc[r] = i;          // self-loop slot
    g_deg[i] = r + 1;       // scatter cursor starts after self loop
}

__global__ void k_scatter(const int* __restrict__ srcp, const int* __restrict__ dstp, int E) {
    int e = blockIdx.x * blockDim.x + threadIdx.x;
    if (e >= E) return;
    int pos = atomicAdd(&g_deg[__ldg(dstp + e)], 1);
    g_csrc[pos] = __ldg(srcp + e);
}

// ---------------- GEMM1: xp1 = x @ W1  (64x64 tile, both operands in smem) ---
// grid (782, 3), 128 threads. Thread micro-tile: 8 rows x 4 cols.
// Per k-step: 2 LDS.128 (rows, bcast) + 1 LDS.128 (weights) + 16 FFMA2.
__global__ void k_gemm1(const float* __restrict__ x, const float* __restrict__ W1) {
    __shared__ float xs[64][72];   // [k][row], 288B stride (16B multiple)
    __shared__ float ws[64][68];   // [k][col], 272B stride (16B multiple)
    int t = threadIdx.x;           // 0..127
    int r0 = blockIdx.x * 64;
    int c0 = blockIdx.y * 64;
    int tr = t >> 4;               // 0..7: rows [tr*8, tr*8+8)
    int tc = t & 15;               // cols [tc*4, tc*4+4)
    unsigned long long acc[4][4];  // [row pair p][col j]
    #pragma unroll
    for (int p = 0; p < 4; p++)
        #pragma unroll
        for (int j = 0; j < 4; j++) acc[p][j] = 0ull;

    for (int k0 = 0; k0 < 128; k0 += 64) {
        __syncthreads();
        for (int i = t; i < 64 * 64; i += 128) {
            int c = i & 63, r = i >> 6;
            xs[c][r] = (r0 + r < NN) ? x[(size_t)(r0 + r) * 128 + k0 + c] : 0.f;
        }
        for (int i = t; i < 64 * 64; i += 128) {
            int c = i & 63, k = i >> 6;
            ws[k][c] = W1[(k0 + k) * 192 + c0 + c];
        }
        __syncthreads();
        #pragma unroll 4
        for (int kk = 0; kk < 64; kk++) {
            float4 wv = *(const float4*)&ws[kk][tc * 4];
            unsigned long long w0 = pk2(wv.x, wv.x), w1 = pk2(wv.y, wv.y);
            unsigned long long w2 = pk2(wv.z, wv.z), w3 = pk2(wv.w, wv.w);
            const ulonglong2* xp = (const ulonglong2*)&xs[kk][tr * 8];
            ulonglong2 q0 = xp[0], q1 = xp[1];   // 4 row pairs
            fma2(acc[0][0], q0.x, w0); fma2(acc[0][1], q0.x, w1);
            fma2(acc[0][2], q0.x, w2); fma2(acc[0][3], q0.x, w3);
            fma2(acc[1][0], q0.y, w0); fma2(acc[1][1], q0.y, w1);
            fma2(acc[1][2], q0.y, w2); fma2(acc[1][3], q0.y, w3);
            fma2(acc[2][0], q1.x, w0); fma2(acc[2][1], q1.x, w1);
            fma2(acc[2][2], q1.x, w2); fma2(acc[2][3], q1.x, w3);
            fma2(acc[3][0], q1.y, w0); fma2(acc[3][1], q1.y, w1);
            fma2(acc[3][2], q1.y, w2); fma2(acc[3][3], q1.y, w3);
        }
    }
    #pragma unroll
    for (int p = 0; p < 4; p++) {
        float lo0, hi0, lo1, hi1, lo2, hi2, lo3, hi3;
        upk2(lo0, hi0, acc[p][0]); upk2(lo1, hi1, acc[p][1]);
        upk2(lo2, hi2, acc[p][2]); upk2(lo3, hi3, acc[p][3]);
        int r = r0 + tr * 8 + 2 * p;
        if (r < NN)
            *(float4*)&g_xp1[(size_t)r * 192 + c0 + tc * 4] = make_float4(lo0, lo1, lo2, lo3);
        if (r + 1 < NN)
            *(float4*)&g_xp1[(size_t)(r + 1) * 192 + c0 + tc * 4] = make_float4(hi0, hi1, hi2, hi3);
    }
}

// ---------------- attention dots, layer 1 (warp per node-head) ----------------
__global__ void k_att1(const float* __restrict__ att_src, const float* __restrict__ att_dst) {
    int idx = blockIdx.x * 8 + (threadIdx.x >> 5);
    if (idx >= NN * H1) return;
    int lane = threadIdx.x & 31;
    int n = idx / 3, h = idx % 3;
    size_t base = (size_t)n * 192 + h * 64;
    float v0 = g_xp1[base + lane], v1 = g_xp1[base + 32 + lane];
    float ss = v0 * att_src[h * 64 + lane] + v1 * att_src[h * 64 + 32 + lane];
    float sd = v0 * att_dst[h * 64 + lane] + v1 * att_dst[h * 64 + 32 + lane];
    ss = warp_sum(ss); sd = warp_sum(sd);
    if (lane == 0) { g_asrc1v[(size_t)n * 4 + h] = ss; g_adst1[idx] = sd; }
}

// ---------------- fused layer1: softmax(no-max) + aggregate + bias + elu ------
__global__ void k_agg1(const float* __restrict__ b1) {
    int d = blockIdx.x * 8 + (threadIdx.x >> 5);
    if (d >= NN) return;
    int lane = threadIdx.x & 31;
    float ad0 = g_adst1[d * 3 + 0], ad1 = g_adst1[d * 3 + 1], ad2 = g_adst1[d * 3 + 2];
    float acc0 = 0.f, acc1 = 0.f, acc2 = 0.f, acc3 = 0.f, acc4 = 0.f, acc5 = 0.f;
    float den0 = 0.f, den1 = 0.f, den2 = 0.f;
    int beg = g_row[d], end = g_row[d + 1];
    int j = beg;
    for (; j + 2 <= end; j += 2) {
        int s0 = __ldg(g_csrc + j), s1 = __ldg(g_csrc + j + 1);
        float4 av0 = __ldg((const float4*)g_asrc1v + s0);
        float4 av1 = __ldg((const float4*)g_asrc1v + s1);
        const float* x0 = g_xp1 + (size_t)s0 * 192 + lane;
        const float* x1 = g_xp1 + (size_t)s1 * 192 + lane;
        float f00 = __ldg(x0),       f01 = __ldg(x0 + 32),  f02 = __ldg(x0 + 64);
        float f03 = __ldg(x0 + 96),  f04 = __ldg(x0 + 128), f05 = __ldg(x0 + 160);
        float f10 = __ldg(x1),       f11 = __ldg(x1 + 32),  f12 = __ldg(x1 + 64);
        float f13 = __ldg(x1 + 96),  f14 = __ldg(x1 + 128), f15 = __ldg(x1 + 160);
        float e00 = __expf(lrelu(av0.x + ad0));
        float e01 = __expf(lrelu(av0.y + ad1));
        float e02 = __expf(lrelu(av0.z + ad2));
        float e10 = __expf(lrelu(av1.x + ad0));
        float e11 = __expf(lrelu(av1.y + ad1));
        float e12 = __expf(lrelu(av1.z + ad2));
        den0 += e00 + e10; den1 += e01 + e11; den2 += e02 + e12;
        acc0 = fmaf(e00, f00, acc0); acc1 = fmaf(e00, f01, acc1);
        acc2 = fmaf(e01, f02, acc2); acc3 = fmaf(e01, f03, acc3);
        acc4 = fmaf(e02, f04, acc4); acc5 = fmaf(e02, f05, acc5);
        acc0 = fmaf(e10, f10, acc0); acc1 = fmaf(e10, f11, acc1);
        acc2 = fmaf(e11, f12, acc2); acc3 = fmaf(e11, f13, acc3);
        acc4 = fmaf(e12, f14, acc4); acc5 = fmaf(e12, f15, acc5);
    }
    if (j < end) {
        int s = __ldg(g_csrc + j);
        float4 av = __ldg((const float4*)g_asrc1v + s);
        const float* xr = g_xp1 + (size_t)s * 192 + lane;
        float e0 = __expf(lrelu(av.x + ad0));
        float e1 = __expf(lrelu(av.y + ad1));
        float e2 = __expf(lrelu(av.z + ad2));
        den0 += e0; den1 += e1; den2 += e2;
        acc0 = fmaf(e0, __ldg(xr),       acc0);
        acc1 = fmaf(e0, __ldg(xr + 32),  acc1);
        acc2 = fmaf(e1, __ldg(xr + 64),  acc2);
        acc3 = fmaf(e1, __ldg(xr + 96),  acc3);
        acc4 = fmaf(e2, __ldg(xr + 128), acc4);
        acc5 = fmaf(e2, __ldg(xr + 160), acc5);
    }
    float i0 = 1.f / fmaxf(den0, 1e-16f);
    float i1 = 1.f / fmaxf(den1, 1e-16f);
    float i2 = 1.f / fmaxf(den2, 1e-16f);
    float* o = g_h1 + (size_t)d * 192 + lane;
    float v;
    v = acc0 * i0 + b1[lane];       o[0]   = v > 0.f ? v : expm1f(v);
    v = acc1 * i0 + b1[lane + 32];  o[32]  = v > 0.f ? v : expm1f(v);
    v = acc2 * i1 + b1[lane + 64];  o[64]  = v > 0.f ? v : expm1f(v);
    v = acc3 * i1 + b1[lane + 96];  o[96]  = v > 0.f ? v : expm1f(v);
    v = acc4 * i2 + b1[lane + 128]; o[128] = v > 0.f ? v : expm1f(v);
    v = acc5 * i2 + b1[lane + 160]; o[160] = v > 0.f ? v : expm1f(v);
}

// ---------------- GEMM2: xp2 = h1 @ W2  (64x64 tile, both operands in smem) ---
__global__ void k_gemm2(const float* __restrict__ W2) {
    __shared__ float xs[64][72];
    __shared__ float ws[64][68];
    int t = threadIdx.x;
    int r0 = blockIdx.x * 64;
    int tr = t >> 4;               // rows [tr*8, tr*8+8)
    int tc = t & 15;               // cols [tc*4, tc*4+4)
    unsigned long long acc[4][4];
    #pragma unroll
    for (int p = 0; p < 4; p++)
        #pragma unroll
        for (int j = 0; j < 4; j++) acc[p][j] = 0ull;

    for (int k0 = 0; k0 < 192; k0 += 64) {
        __syncthreads();
        for (int i = t; i < 64 * 64; i += 128) {
            int c = i & 63, r = i >> 6;
            xs[c][r] = (r0 + r < NN) ? g_h1[(size_t)(r0 + r) * 192 + k0 + c] : 0.f;
        }
        for (int i = t; i < 64 * 64; i += 128) {
            int c = i & 63, k = i >> 6;
            ws[k][c] = W2[(k0 + k) * 64 + c];
        }
        __syncthreads();
        #pragma unroll 4
        for (int kk = 0; kk < 64; kk++) {
            float4 wv = *(const float4*)&ws[kk][tc * 4];
            unsigned long long w0 = pk2(wv.x, wv.x), w1 = pk2(wv.y, wv.y);
            unsigned long long w2 = pk2(wv.z, wv.z), w3 = pk2(wv.w, wv.w);
            const ulonglong2* xp = (const ulonglong2*)&xs[kk][tr * 8];
            ulonglong2 q0 = xp[0], q1 = xp[1];
            fma2(acc[0][0], q0.x, w0); fma2(acc[0][1], q0.x, w1);
            fma2(acc[0][2], q0.x, w2); fma2(acc[0][3], q0.x, w3);
            fma2(acc[1][0], q0.y, w0); fma2(acc[1][1], q0.y, w1);
            fma2(acc[1][2], q0.y, w2); fma2(acc[1][3], q0.y, w3);
            fma2(acc[2][0], q1.x, w0); fma2(acc[2][1], q1.x, w1);
            fma2(acc[2][2], q1.x, w2); fma2(acc[2][3], q1.x, w3);
            fma2(acc[3][0], q1.y, w0); fma2(acc[3][1], q1.y, w1);
            fma2(acc[3][2], q1.y, w2); fma2(acc[3][3], q1.y, w3);
        }
    }
    #pragma unroll
    for (int p = 0; p < 4; p++) {
        float lo0, hi0, lo1, hi1, lo2, hi2, lo3, hi3;
        upk2(lo0, hi0, acc[p][0]); upk2(lo1, hi1, acc[p][1]);
        upk2(lo2, hi2, acc[p][2]); upk2(lo3, hi3, acc[p][3]);
        int r = r0 + tr * 8 + 2 * p;
        if (r < NN)
            *(float4*)&g_xp2[(size_t)r * 64 + tc * 4] = make_float4(lo0, lo1, lo2, lo3);
        if (r + 1 < NN)
            *(float4*)&g_xp2[(size_t)(r + 1) * 64 + tc * 4] = make_float4(hi0, hi1, hi2, hi3);
    }
}

// ---------------- attention dots, layer 2 (warp per node) ---------------------
__global__ void k_att2(const float* __restrict__ att_src, const float* __restrict__ att_dst) {
    int n = blockIdx.x * 8 + (threadIdx.x >> 5);
    if (n >= NN) return;
    int lane = threadIdx.x & 31;
    size_t base = (size_t)n * 64;
    float v0 = g_xp2[base + lane], v1 = g_xp2[base + 32 + lane];
    float ss = v0 * att_src[lane] + v1 * att_src[32 + lane];
    float sd = v0 * att_dst[lane] + v1 * att_dst[32 + lane];
    ss = warp_sum(ss); sd = warp_sum(sd);
    if (lane == 0) { g_asrc2[n] = ss; g_adst2[n] = sd; }
}

// ---------------- fused layer2: softmax + aggregate + bias + pool -------------
__global__ void k_agg2(const float* __restrict__ b2, const int* __restrict__ batch) {
    int d = blockIdx.x * 8 + (threadIdx.x >> 5);
    if (d >= NN) return;
    int lane = threadIdx.x & 31;
    float ad = g_adst2[d];
    float acc0 = 0.f, acc1 = 0.f, den = 0.f;
    int beg = g_row[d], end = g_row[d + 1];
    int j = beg;
    for (; j + 2 <= end; j += 2) {
        int s0 = __ldg(g_csrc + j), s1 = __ldg(g_csrc + j + 1);
        float a0 = __ldg(g_asrc2 + s0), a1 = __ldg(g_asrc2 + s1);
        const float* x0 = g_xp2 + (size_t)s0 * 64 + lane;
        const float* x1 = g_xp2 + (size_t)s1 * 64 + lane;
        float f00 = __ldg(x0), f01 = __ldg(x0 + 32);
        float f10 = __ldg(x1), f11 = __ldg(x1 + 32);
        float e0 = __expf(lrelu(a0 + ad));
        float e1 = __expf(lrelu(a1 + ad));
        den += e0 + e1;
        acc0 = fmaf(e0, f00, acc0); acc1 = fmaf(e0, f01, acc1);
        acc0 = fmaf(e1, f10, acc0); acc1 = fmaf(e1, f11, acc1);
    }
    if (j < end) {
        int s = __ldg(g_csrc + j);
        float e = __expf(lrelu(__ldg(g_asrc2 + s) + ad));
        den += e;
        const float* xr = g_xp2 + (size_t)s * 64 + lane;
        acc0 = fmaf(e, __ldg(xr),      acc0);
        acc1 = fmaf(e, __ldg(xr + 32), acc1);
    }
    float inv = 1.f / fmaxf(den, 1e-16f);
    int b = __ldg(batch + d);
    atomicAdd(&g_pool[b * 64 + lane],      acc0 * inv + b2[lane]);
    atomicAdd(&g_pool[b * 64 + lane + 32], acc1 * inv + b2[lane + 32]);
    if (lane == 0) atomicAdd(&g_cnt[b], 1.0f);
}

// ---------------- final: (pool/cnt) @ lin_W + lin_b ---------------------------
__global__ void k_final(const float* __restrict__ lin_W, const float* __restrict__ lin_b,
                        float* __restrict__ out) {
    int t = blockIdx.x * blockDim.x + threadIdx.x;
    if (t >= NG * 10) return;
    int g = t / 10, j = t % 10;
    float inv = 1.0f / fmaxf(g_cnt[g], 1.0f);
    float acc = lin_b[j];
    #pragma unroll 8
    for (int c = 0; c < 64; c++)
        acc += g_pool[g * 64 + c] * inv * lin_W[c * 10 + j];
    out[t] = acc;
}

// ---------------- host launch -------------------------------------------------
extern "C" void kernel_launch(void* const* d_in, const int* in_sizes, int n_in,
                              void* d_out, int out_size) {
    const float* x        = (const float*)d_in[0];
    const int*   ei       = (const int*)  d_in[1];
    const int*   batch    = (const int*)  d_in[2];
    const float* W1       = (const float*)d_in[3];
    const float* att_src1 = (const float*)d_in[4];
    const float* att_dst1 = (const float*)d_in[5];
    const float* b1       = (const float*)d_in[6];
    const float* W2       = (const float*)d_in[7];
    const float* att_src2 = (const float*)d_in[8];
    const float* att_dst2 = (const float*)d_in[9];
    const float* b2       = (const float*)d_in[10];
    const float* lin_W    = (const float*)d_in[11];
    const float* lin_b    = (const float*)d_in[12];
    float* out = (float*)d_out;

    int E = in_sizes[1] / 2;            // 800000
    const int* srcp = ei;
    const int* dstp = ei + E;

    // launch index 3 = k_gemm1 (profiler capture lands on index 3)
    k_init_a<<<(NN + 255) / 256, 256>>>();                 // 0: deg=1
    k_init_b<<<(NG * D2 + 255) / 256, 256>>>();            // 1: pool=0
    k_hist<<<(E + 255) / 256, 256>>>(dstp, E);             // 2: degree histogram
    k_gemm1<<<dim3((NN + 63) / 64, 3), 128>>>(x, W1);      // 3: PROFILED
    k_scan_blk<<<NBLK, 256>>>();                           // 4: block scans
    k_scan_top<<<1, 256>>>();                              // 5: scan of block sums
    k_csr_fin<<<NBLK, 256>>>();                            // 6: offsets + self loop + cursor
    k_scatter<<<(E + 255) / 256, 256>>>(srcp, dstp, E);    // 7: fill CSR

    // layer 1
    k_att1<<<(NN * H1 + 7) / 8, 256>>>(att_src1, att_dst1);
    k_agg1<<<(NN + 7) / 8, 256>>>(b1);

    // layer 2
    k_gemm2<<<(NN + 63) / 64, 128>>>(W2);
    k_att2<<<(NN + 7) / 8, 256>>>(att_src2, att_dst2);
    k_agg2<<<(NN + 7) / 8, 256>>>(b2, batch);

    // readout
    k_final<<<10, 128>>>(lin_W, lin_b, out);
}

// round 11
// speedup vs baseline: 1.4695x; 1.0709x over previous
#include <cuda_runtime.h>

// Problem-fixed shapes
#define NN 50000
#define EE 800000
#define TT (EE + NN)      // real edges + self loops
#define H1 3
#define D1 192            // 3 heads x 64
#define D2 64
#define NG 128
#define NBLK ((NN + 255) / 256)   // 196 scan blocks

// ---------------- scratch (device globals; no runtime allocation) -----------
__device__ float g_xp1[(size_t)NN * D1];   // layer1 lin output
__device__ float g_h1[(size_t)NN * D1];    // elu(agg + b1)
__device__ float g_asrc1v[(size_t)NN * 4]; // float4-padded src logits (3 heads + pad)
__device__ float g_adst1[NN * H1];
__device__ float g_xp2[(size_t)NN * D2];
__device__ float g_asrc2[NN];
__device__ float g_adst2[NN];
__device__ float g_pool[NG * D2];
__device__ float g_cnt[NG];
__device__ float g_u_src[H1 * 128];        // W1^T @ att_src per head
__device__ float g_u_dst[H1 * 128];        // W1^T @ att_dst per head
// CSR (rebuilt every call; deterministic content, order-free use)
__device__ int   g_deg[NN];        // degree, then reused as scatter cursor
__device__ int   g_row[NN + 1];    // row offsets
__device__ int   g_csrc[TT];       // src node per CSR slot
__device__ int   g_bsum[NBLK];     // per-block degree sums
__device__ int   g_boff[NBLK];     // exclusive block offsets

// ---------------- helpers ----------------------------------------------------
__device__ __forceinline__ float warp_sum(float s) {
    #pragma unroll
    for (int o = 16; o; o >>= 1) s += __shfl_xor_sync(0xFFFFFFFFu, s, o);
    return s;
}
__device__ __forceinline__ float lrelu(float a) { return fmaxf(a, 0.2f * a); }
__device__ __forceinline__ unsigned long long pk2(float lo, float hi) {
    unsigned long long r;
    asm("mov.b64 %0, {%1, %2};" : "=l"(r) : "f"(lo), "f"(hi));
    return r;
}
__device__ __forceinline__ void upk2(float& lo, float& hi, unsigned long long v) {
    asm("mov.b64 {%0, %1}, %2;" : "=f"(lo), "=f"(hi) : "l"(v));
}
__device__ __forceinline__ void fma2(unsigned long long& acc, unsigned long long a,
                                     unsigned long long b) {
    asm("fma.rn.f32x2 %0, %1, %2, %0;" : "+l"(acc) : "l"(a), "l"(b));
}

// ---------------- init (merged) -----------------------------------------------
__global__ void k_init() {
    int i = blockIdx.x * blockDim.x + threadIdx.x;
    if (i < NN) g_deg[i] = 1;            // self loop
    if (i < NG * D2) g_pool[i] = 0.f;
    if (i < NG) g_cnt[i] = 0.f;
}

// ---------------- u = W1^T @ att  (block = head, 128 threads = k) -------------
__global__ void k_prep_u(const float* __restrict__ W1, const float* __restrict__ attS,
                         const float* __restrict__ attD) {
    int h = blockIdx.x, k = threadIdx.x;
    const float* wr = W1 + (size_t)k * 192 + h * 64;
    const float* as = attS + h * 64;
    const float* ad = attD + h * 64;
    float us = 0.f, ud = 0.f;
    #pragma unroll 8
    for (int c = 0; c < 64; c++) {
        float w = wr[c];
        us = fmaf(w, as[c], us);
        ud = fmaf(w, ad[c], ud);
    }
    g_u_src[h * 128 + k] = us;
    g_u_dst[h * 128 + k] = ud;
}

// ---------------- layer1 attention dots directly from x (warp per node) -------
__global__ void k_att1x(const float* __restrict__ x) {
    int n = blockIdx.x * 8 + (threadIdx.x >> 5);
    if (n >= NN) return;
    int lane = threadIdx.x & 31;
    const float* xr = x + (size_t)n * 128;
    float x0 = __ldg(xr + lane),      x1 = __ldg(xr + lane + 32);
    float x2 = __ldg(xr + lane + 64), x3 = __ldg(xr + lane + 96);
    #pragma unroll
    for (int h = 0; h < 3; h++) {
        const float* us = g_u_src + h * 128;
        const float* ud = g_u_dst + h * 128;
        float ss = x0 * us[lane] + x1 * us[lane + 32] + x2 * us[lane + 64] + x3 * us[lane + 96];
        float sd = x0 * ud[lane] + x1 * ud[lane + 32] + x2 * ud[lane + 64] + x3 * ud[lane + 96];
        ss = warp_sum(ss); sd = warp_sum(sd);
        if (lane == 0) { g_asrc1v[(size_t)n * 4 + h] = ss; g_adst1[n * 3 + h] = sd; }
    }
}

// ---------------- CSR build ---------------------------------------------------
__global__ void k_hist(const int* __restrict__ dstp, int E) {
    int e = blockIdx.x * blockDim.x + threadIdx.x;
    if (e < E) atomicAdd(&g_deg[__ldg(dstp + e)], 1);
}

__global__ void k_scan_blk() {
    __shared__ int sd[256];
    int t = threadIdx.x;
    int i = blockIdx.x * 256 + t;
    int v = (i < NN) ? g_deg[i] : 0;
    sd[t] = v;
    __syncthreads();
    #pragma unroll
    for (int off = 1; off < 256; off <<= 1) {
        int u = (t >= off) ? sd[t - off] : 0;
        __syncthreads();
        sd[t] += u;
        __syncthreads();
    }
    if (i < NN) g_row[i] = sd[t] - v;
    if (t == 255) g_bsum[blockIdx.x] = sd[255];
}

__global__ void k_scan_top() {
    __shared__ int sd[256];
    int t = threadIdx.x;
    int v = (t < NBLK) ? g_bsum[t] : 0;
    sd[t] = v;
    __syncthreads();
    #pragma unroll
    for (int off = 1; off < 256; off <<= 1) {
        int u = (t >= off) ? sd[t - off] : 0;
        __syncthreads();
        sd[t] += u;
        __syncthreads();
    }
    if (t < NBLK) g_boff[t] = sd[t] - v;
    if (t == 255) g_row[NN] = sd[255];
}

__global__ void k_csr_fin() {
    int i = blockIdx.x * 256 + threadIdx.x;
    if (i >= NN) return;
    int r = g_row[i] + g_boff[blockIdx.x];
    g_row[i] = r;
    g_csrc[r] = i;          // self-loop slot
    g_deg[i] = r + 1;       // scatter cursor starts after self loop
}

__global__ void k_scatter(const int* __restrict__ srcp, const int* __restrict__ dstp, int E) {
    int e = blockIdx.x * blockDim.x + threadIdx.x;
    if (e >= E) return;
    int pos = atomicAdd(&g_deg[__ldg(dstp + e)], 1);
    g_csrc[pos] = __ldg(srcp + e);
}

// ---------------- GEMM1: xp1 = x @ W1  (64x64 tile, both operands in smem) ---
__global__ void k_gemm1(const float* __restrict__ x, const float* __restrict__ W1) {
    __shared__ float xs[64][72];
    __shared__ float ws[64][68];
    int t = threadIdx.x;           // 0..127
    int r0 = blockIdx.x * 64;
    int c0 = blockIdx.y * 64;
    int tr = t >> 4;               // rows [tr*8, tr*8+8)
    int tc = t & 15;               // cols [tc*4, tc*4+4)
    unsigned long long acc[4][4];
    #pragma unroll
    for (int p = 0; p < 4; p++)
        #pragma unroll
        for (int j = 0; j < 4; j++) acc[p][j] = 0ull;

    for (int k0 = 0; k0 < 128; k0 += 64) {
        __syncthreads();
        for (int i = t; i < 64 * 64; i += 128) {
            int c = i & 63, r = i >> 6;
            xs[c][r] = (r0 + r < NN) ? x[(size_t)(r0 + r) * 128 + k0 + c] : 0.f;
        }
        for (int i = t; i < 64 * 64; i += 128) {
            int c = i & 63, k = i >> 6;
            ws[k][c] = W1[(k0 + k) * 192 + c0 + c];
        }
        __syncthreads();
        #pragma unroll 4
        for (int kk = 0; kk < 64; kk++) {
            float4 wv = *(const float4*)&ws[kk][tc * 4];
            unsigned long long w0 = pk2(wv.x, wv.x), w1 = pk2(wv.y, wv.y);
            unsigned long long w2 = pk2(wv.z, wv.z), w3 = pk2(wv.w, wv.w);
            const ulonglong2* xp = (const ulonglong2*)&xs[kk][tr * 8];
            ulonglong2 q0 = xp[0], q1 = xp[1];
            fma2(acc[0][0], q0.x, w0); fma2(acc[0][1], q0.x, w1);
            fma2(acc[0][2], q0.x, w2); fma2(acc[0][3], q0.x, w3);
            fma2(acc[1][0], q0.y, w0); fma2(acc[1][1], q0.y, w1);
            fma2(acc[1][2], q0.y, w2); fma2(acc[1][3], q0.y, w3);
            fma2(acc[2][0], q1.x, w0); fma2(acc[2][1], q1.x, w1);
            fma2(acc[2][2], q1.x, w2); fma2(acc[2][3], q1.x, w3);
            fma2(acc[3][0], q1.y, w0); fma2(acc[3][1], q1.y, w1);
            fma2(acc[3][2], q1.y, w2); fma2(acc[3][3], q1.y, w3);
        }
    }
    #pragma unroll
    for (int p = 0; p < 4; p++) {
        float lo0, hi0, lo1, hi1, lo2, hi2, lo3, hi3;
        upk2(lo0, hi0, acc[p][0]); upk2(lo1, hi1, acc[p][1]);
        upk2(lo2, hi2, acc[p][2]); upk2(lo3, hi3, acc[p][3]);
        int r = r0 + tr * 8 + 2 * p;
        if (r < NN)
            *(float4*)&g_xp1[(size_t)r * 192 + c0 + tc * 4] = make_float4(lo0, lo1, lo2, lo3);
        if (r + 1 < NN)
            *(float4*)&g_xp1[(size_t)(r + 1) * 192 + c0 + tc * 4] = make_float4(hi0, hi1, hi2, hi3);
    }
}

// ---------------- fused layer1: softmax(no-max) + aggregate + bias + elu ------
__global__ void k_agg1(const float* __restrict__ b1) {
    int d = blockIdx.x * 8 + (threadIdx.x >> 5);
    if (d >= NN) return;
    int lane = threadIdx.x & 31;
    float ad0 = g_adst1[d * 3 + 0], ad1 = g_adst1[d * 3 + 1], ad2 = g_adst1[d * 3 + 2];
    float acc0 = 0.f, acc1 = 0.f, acc2 = 0.f, acc3 = 0.f, acc4 = 0.f, acc5 = 0.f;
    float den0 = 0.f, den1 = 0.f, den2 = 0.f;
    int beg = g_row[d], end = g_row[d + 1];
    int j = beg;
    for (; j + 2 <= end; j += 2) {
        int s0 = __ldg(g_csrc + j), s1 = __ldg(g_csrc + j + 1);
        float4 av0 = __ldg((const float4*)g_asrc1v + s0);
        float4 av1 = __ldg((const float4*)g_asrc1v + s1);
        const float* x0 = g_xp1 + (size_t)s0 * 192 + lane;
        const float* x1 = g_xp1 + (size_t)s1 * 192 + lane;
        float f00 = __ldg(x0),       f01 = __ldg(x0 + 32),  f02 = __ldg(x0 + 64);
        float f03 = __ldg(x0 + 96),  f04 = __ldg(x0 + 128), f05 = __ldg(x0 + 160);
        float f10 = __ldg(x1),       f11 = __ldg(x1 + 32),  f12 = __ldg(x1 + 64);
        float f13 = __ldg(x1 + 96),  f14 = __ldg(x1 + 128), f15 = __ldg(x1 + 160);
        float e00 = __expf(lrelu(av0.x + ad0));
        float e01 = __expf(lrelu(av0.y + ad1));
        float e02 = __expf(lrelu(av0.z + ad2));
        float e10 = __expf(lrelu(av1.x + ad0));
        float e11 = __expf(lrelu(av1.y + ad1));
        float e12 = __expf(lrelu(av1.z + ad2));
        den0 += e00 + e10; den1 += e01 + e11; den2 += e02 + e12;
        acc0 = fmaf(e00, f00, acc0); acc1 = fmaf(e00, f01, acc1);
        acc2 = fmaf(e01, f02, acc2); acc3 = fmaf(e01, f03, acc3);
        acc4 = fmaf(e02, f04, acc4); acc5 = fmaf(e02, f05, acc5);
        acc0 = fmaf(e10, f10, acc0); acc1 = fmaf(e10, f11, acc1);
        acc2 = fmaf(e11, f12, acc2); acc3 = fmaf(e11, f13, acc3);
        acc4 = fmaf(e12, f14, acc4); acc5 = fmaf(e12, f15, acc5);
    }
    if (j < end) {
        int s = __ldg(g_csrc + j);
        float4 av = __ldg((const float4*)g_asrc1v + s);
        const float* xr = g_xp1 + (size_t)s * 192 + lane;
        float e0 = __expf(lrelu(av.x + ad0));
        float e1 = __expf(lrelu(av.y + ad1));
        float e2 = __expf(lrelu(av.z + ad2));
        den0 += e0; den1 += e1; den2 += e2;
        acc0 = fmaf(e0, __ldg(xr),       acc0);
        acc1 = fmaf(e0, __ldg(xr + 32),  acc1);
        acc2 = fmaf(e1, __ldg(xr + 64),  acc2);
        acc3 = fmaf(e1, __ldg(xr + 96),  acc3);
        acc4 = fmaf(e2, __ldg(xr + 128), acc4);
        acc5 = fmaf(e2, __ldg(xr + 160), acc5);
    }
    float i0 = 1.f / fmaxf(den0, 1e-16f);
    float i1 = 1.f / fmaxf(den1, 1e-16f);
    float i2 = 1.f / fmaxf(den2, 1e-16f);
    float* o = g_h1 + (size_t)d * 192 + lane;
    float v;
    v = acc0 * i0 + b1[lane];       o[0]   = v > 0.f ? v : expm1f(v);
    v = acc1 * i0 + b1[lane + 32];  o[32]  = v > 0.f ? v : expm1f(v);
    v = acc2 * i1 + b1[lane + 64];  o[64]  = v > 0.f ? v : expm1f(v);
    v = acc3 * i1 + b1[lane + 96];  o[96]  = v > 0.f ? v : expm1f(v);
    v = acc4 * i2 + b1[lane + 128]; o[128] = v > 0.f ? v : expm1f(v);
    v = acc5 * i2 + b1[lane + 160]; o[160] = v > 0.f ? v : expm1f(v);
}

// ---------------- GEMM2: xp2 = h1 @ W2  (64x64 tile) --------------------------
__global__ void k_gemm2(const float* __restrict__ W2) {
    __shared__ float xs[64][72];
    __shared__ float ws[64][68];
    int t = threadIdx.x;
    int r0 = blockIdx.x * 64;
    int tr = t >> 4;
    int tc = t & 15;
    unsigned long long acc[4][4];
    #pragma unroll
    for (int p = 0; p < 4; p++)
        #pragma unroll
        for (int j = 0; j < 4; j++) acc[p][j] = 0ull;

    for (int k0 = 0; k0 < 192; k0 += 64) {
        __syncthreads();
        for (int i = t; i < 64 * 64; i += 128) {
            int c = i & 63, r = i >> 6;
            xs[c][r] = (r0 + r < NN) ? g_h1[(size_t)(r0 + r) * 192 + k0 + c] : 0.f;
        }
        for (int i = t; i < 64 * 64; i += 128) {
            int c = i & 63, k = i >> 6;
            ws[k][c] = W2[(k0 + k) * 64 + c];
        }
        __syncthreads();
        #pragma unroll 4
        for (int kk = 0; kk < 64; kk++) {
            float4 wv = *(const float4*)&ws[kk][tc * 4];
            unsigned long long w0 = pk2(wv.x, wv.x), w1 = pk2(wv.y, wv.y);
            unsigned long long w2 = pk2(wv.z, wv.z), w3 = pk2(wv.w, wv.w);
            const ulonglong2* xp = (const ulonglong2*)&xs[kk][tr * 8];
            ulonglong2 q0 = xp[0], q1 = xp[1];
            fma2(acc[0][0], q0.x, w0); fma2(acc[0][1], q0.x, w1);
            fma2(acc[0][2], q0.x, w2); fma2(acc[0][3], q0.x, w3);
            fma2(acc[1][0], q0.y, w0); fma2(acc[1][1], q0.y, w1);
            fma2(acc[1][2], q0.y, w2); fma2(acc[1][3], q0.y, w3);
            fma2(acc[2][0], q1.x, w0); fma2(acc[2][1], q1.x, w1);
            fma2(acc[2][2], q1.x, w2); fma2(acc[2][3], q1.x, w3);
            fma2(acc[3][0], q1.y, w0); fma2(acc[3][1], q1.y, w1);
            fma2(acc[3][2], q1.y, w2); fma2(acc[3][3], q1.y, w3);
        }
    }
    #pragma unroll
    for (int p = 0; p < 4; p++) {
        float lo0, hi0, lo1, hi1, lo2, hi2, lo3, hi3;
        upk2(lo0, hi0, acc[p][0]); upk2(lo1, hi1, acc[p][1]);
        upk2(lo2, hi2, acc[p][2]); upk2(lo3, hi3, acc[p][3]);
        int r = r0 + tr * 8 + 2 * p;
        if (r < NN)
            *(float4*)&g_xp2[(size_t)r * 64 + tc * 4] = make_float4(lo0, lo1, lo2, lo3);
        if (r + 1 < NN)
            *(float4*)&g_xp2[(size_t)(r + 1) * 64 + tc * 4] = make_float4(hi0, hi1, hi2, hi3);
    }
}

// ---------------- attention dots, layer 2 (warp per node) ---------------------
__global__ void k_att2(const float* __restrict__ att_src, const float* __restrict__ att_dst) {
    int n = blockIdx.x * 8 + (threadIdx.x >> 5);
    if (n >= NN) return;
    int lane = threadIdx.x & 31;
    size_t base = (size_t)n * 64;
    float v0 = g_xp2[base + lane], v1 = g_xp2[base + 32 + lane];
    float ss = v0 * att_src[lane] + v1 * att_src[32 + lane];
    float sd = v0 * att_dst[lane] + v1 * att_dst[32 + lane];
    ss = warp_sum(ss); sd = warp_sum(sd);
    if (lane == 0) { g_asrc2[n] = ss; g_adst2[n] = sd; }
}

// ---------------- fused layer2: softmax + aggregate + bias + pool -------------
__global__ void k_agg2(const float* __restrict__ b2, const int* __restrict__ batch) {
    int d = blockIdx.x * 8 + (threadIdx.x >> 5);
    if (d >= NN) return;
    int lane = threadIdx.x & 31;
    float ad = g_adst2[d];
    float acc0 = 0.f, acc1 = 0.f, den = 0.f;
    int beg = g_row[d], end = g_row[d + 1];
    int j = beg;
    for (; j + 2 <= end; j += 2) {
        int s0 = __ldg(g_csrc + j), s1 = __ldg(g_csrc + j + 1);
        float a0 = __ldg(g_asrc2 + s0), a1 = __ldg(g_asrc2 + s1);
        const float* x0 = g_xp2 + (size_t)s0 * 64 + lane;
        const float* x1 = g_xp2 + (size_t)s1 * 64 + lane;
        float f00 = __ldg(x0), f01 = __ldg(x0 + 32);
        float f10 = __ldg(x1), f11 = __ldg(x1 + 32);
        float e0 = __expf(lrelu(a0 + ad));
        float e1 = __expf(lrelu(a1 + ad));
        den += e0 + e1;
        acc0 = fmaf(e0, f00, acc0); acc1 = fmaf(e0, f01, acc1);
        acc0 = fmaf(e1, f10, acc0); acc1 = fmaf(e1, f11, acc1);
    }
    if (j < end) {
        int s = __ldg(g_csrc + j);
        float e = __expf(lrelu(__ldg(g_asrc2 + s) + ad));
        den += e;
        const float* xr = g_xp2 + (size_t)s * 64 + lane;
        acc0 = fmaf(e, __ldg(xr),      acc0);
        acc1 = fmaf(e, __ldg(xr + 32), acc1);
    }
    float inv = 1.f / fmaxf(den, 1e-16f);
    int b = __ldg(batch + d);
    atomicAdd(&g_pool[b * 64 + lane],      acc0 * inv + b2[lane]);
    atomicAdd(&g_pool[b * 64 + lane + 32], acc1 * inv + b2[lane + 32]);
    if (lane == 0) atomicAdd(&g_cnt[b], 1.0f);
}

// ---------------- final: (pool/cnt) @ lin_W + lin_b ---------------------------
__global__ void k_final(const float* __restrict__ lin_W, const float* __restrict__ lin_b,
                        float* __restrict__ out) {
    int t = blockIdx.x * blockDim.x + threadIdx.x;
    if (t >= NG * 10) return;
    int g = t / 10, j = t % 10;
    float inv = 1.0f / fmaxf(g_cnt[g], 1.0f);
    float acc = lin_b[j];
    #pragma unroll 8
    for (int c = 0; c < 64; c++)
        acc += g_pool[g * 64 + c] * inv * lin_W[c * 10 + j];
    out[t] = acc;
}

// ---------------- host launch -------------------------------------------------
extern "C" void kernel_launch(void* const* d_in, const int* in_sizes, int n_in,
                              void* d_out, int out_size) {
    const float* x        = (const float*)d_in[0];
    const int*   ei       = (const int*)  d_in[1];
    const int*   batch    = (const int*)  d_in[2];
    const float* W1       = (const float*)d_in[3];
    const float* att_src1 = (const float*)d_in[4];
    const float* att_dst1 = (const float*)d_in[5];
    const float* b1       = (const float*)d_in[6];
    const float* W2       = (const float*)d_in[7];
    const float* att_src2 = (const float*)d_in[8];
    const float* att_dst2 = (const float*)d_in[9];
    const float* b2       = (const float*)d_in[10];
    const float* lin_W    = (const float*)d_in[11];
    const float* lin_b    = (const float*)d_in[12];
    float* out = (float*)d_out;

    int E = in_sizes[1] / 2;            // 800000
    const int* srcp = ei;
    const int* dstp = ei + E;

    // Side stream for the CSR build + layer1 attention dots (independent of GEMM1)
    cudaStream_t s1;
    cudaStreamCreate(&s1);
    cudaEvent_t evF, evJ;
    cudaEventCreateWithFlags(&evF, cudaEventDisableTiming);
    cudaEventCreateWithFlags(&evJ, cudaEventDisableTiming);

    k_init<<<(NN + 255) / 256, 256>>>();                        // L0 (s0)
    cudaEventRecord(evF, 0);
    cudaStreamWaitEvent(s1, evF, 0);

    k_prep_u<<<3, 128, 0, s1>>>(W1, att_src1, att_dst1);        // L1 (s1)
    k_hist<<<(E + 255) / 256, 256, 0, s1>>>(dstp, E);           // L2 (s1)
    k_gemm1<<<dim3((NN + 63) / 64, 3), 128>>>(x, W1);           // L3 (s0) PROFILED
    k_att1x<<<(NN + 7) / 8, 256, 0, s1>>>(x);                   // L4 (s1)
    k_scan_blk<<<NBLK, 256, 0, s1>>>();                         // L5 (s1)
    k_scan_top<<<1, 256, 0, s1>>>();                            // L6 (s1)
    k_csr_fin<<<NBLK, 256, 0, s1>>>();                          // L7 (s1)
    k_scatter<<<(E + 255) / 256, 256, 0, s1>>>(srcp, dstp, E);  // L8 (s1)

    cudaEventRecord(evJ, s1);
    cudaStreamWaitEvent(0, evJ, 0);

    // layer 1 aggregation (needs gemm1 + att1x + CSR)
    k_agg1<<<(NN + 7) / 8, 256>>>(b1);

    // layer 2
    k_gemm2<<<(NN + 63) / 64, 128>>>(W2);
    k_att2<<<(NN + 7) / 8, 256>>>(att_src2, att_dst2);
    k_agg2<<<(NN + 7) / 8, 256>>>(b2, batch);

    // readout
    k_final<<<10, 128>>>(lin_W, lin_b, out);

    cudaEventDestroy(evF);
    cudaEventDestroy(evJ);
    cudaStreamDestroy(s1);
}